// round 12
// baseline (speedup 1.0000x reference)
#include <cuda_runtime.h>
#include <cuda_bf16.h>

typedef unsigned long long u64;
typedef unsigned int u32;

// ---------------------------------------------------------------------------
// Shapes: B=8, C=64, N=512, T=64, valid L=58 (stored padded to 64).
// fp32 pool: q0..q9 (ids 0-9; 4 and 9 unused as fp32), ACC=12.
// bf16 pool slots (BUFSZ each):
//   0/1 seed1(q4) hi/lo, 2/3 & 4/5 branch0 ping-pong,
//   6/7 seed2(q9) hi/lo, 8/9 & 10/11 branch1 ping-pong.
// Node step: r' = q + d∘r + A'·r  with d = diag(M)-1 (fp32, epilogue) and
// A' = M - diag(M) (tiny entries ~4e-3, plain bf16, 2 MMA products).
// ---------------------------------------------------------------------------
#define BUFSZ (8ULL*64ULL*512ULL*64ULL)

__device__ float g_pool[13ULL*BUFSZ];
__device__ __nv_bfloat16 g_bf[12ULL*BUFSZ];
__device__ __nv_bfloat16 g_Abf[4ULL*512*512];  // slots 0,2 used: [asel*2][v][w] of A'
__device__ float g_dA[2*512];                  // diag(M)-1 per branch

__device__ float g_An [512*512];   // [w][v] = M1[v][w]
__device__ float g_AnT[512*512];   // [w][v] = M2[v][w]
__device__ float g_rd1[512], g_rd2[512];
__device__ __nv_bfloat16 g_W7h[128*448];   // [o][kd] hi
__device__ __nv_bfloat16 g_W7l[128*448];   // [o][kd] lo
__device__ float g_b7[128];
__device__ __nv_bfloat16 g_Wqh[10*64*64];  // [m][out][in] hi  (MMA A-row = out)
__device__ __nv_bfloat16 g_Wql[10*64*64];  // [m][out][in] lo
__device__ float g_bias[64];

// ---------------------------------------------------------------------------
// helpers
// ---------------------------------------------------------------------------
__device__ __forceinline__ u32 smem_u32(const void* p){
    u32 a;
    asm("{ .reg .u64 t; cvta.to.shared.u64 t, %1; cvt.u32.u64 %0, t; }" : "=r"(a) : "l"(p));
    return a;
}
// split a pair of fp32 into packed bf16 hi / bf16 lo
__device__ __forceinline__ void split2(float a0, float a1, u32& hi, u32& lo){
    __nv_bfloat16 h0 = __float2bfloat16(a0);
    __nv_bfloat16 h1 = __float2bfloat16(a1);
    float r0 = a0 - __bfloat162float(h0);
    float r1 = a1 - __bfloat162float(h1);
    union { __nv_bfloat162 v; u32 u; } ch, cl;
    ch.v = __halves2bfloat162(h0, h1);
    cl.v = __halves2bfloat162(__float2bfloat16(r0), __float2bfloat16(r1));
    hi = ch.u; lo = cl.u;
}
__device__ __forceinline__ float2 bf2f2(u32 u){
    union { u32 u; __nv_bfloat162 v; } c; c.u = u;
    return __bfloat1622float2(c.v);
}

// ---------------------------------------------------------------------------
// mma.sync / ldmatrix / cp.async wrappers (baseline PTX, legal on compute_103)
// ---------------------------------------------------------------------------
__device__ __forceinline__ void mma16816(float* c, const u32* a, u32 b0, u32 b1){
    asm volatile(
        "mma.sync.aligned.m16n8k16.row.col.f32.bf16.bf16.f32 "
        "{%0,%1,%2,%3}, {%4,%5,%6,%7}, {%8,%9}, {%0,%1,%2,%3};"
        : "+f"(c[0]), "+f"(c[1]), "+f"(c[2]), "+f"(c[3])
        : "r"(a[0]), "r"(a[1]), "r"(a[2]), "r"(a[3]), "r"(b0), "r"(b1));
}
__device__ __forceinline__ void ldmA(u32* r, u32 addr){
    asm volatile("ldmatrix.sync.aligned.m8n8.x4.shared.b16 {%0,%1,%2,%3}, [%4];"
        : "=r"(r[0]), "=r"(r[1]), "=r"(r[2]), "=r"(r[3]) : "r"(addr));
}
__device__ __forceinline__ void ldmBT(u32* r, u32 addr){
    asm volatile("ldmatrix.sync.aligned.m8n8.x4.trans.shared.b16 {%0,%1,%2,%3}, [%4];"
        : "=r"(r[0]), "=r"(r[1]), "=r"(r[2]), "=r"(r[3]) : "r"(addr));
}
__device__ __forceinline__ void cpa16(u32 dst, const void* src){
    asm volatile("cp.async.cg.shared.global [%0], [%1], 16;" :: "r"(dst), "l"(src));
}
__device__ __forceinline__ void cpa_commit(){
    asm volatile("cp.async.commit_group;" ::: "memory");
}
template<int N>
__device__ __forceinline__ void cpa_wait(){
    asm volatile("cp.async.wait_group %0;" :: "n"(N) : "memory");
}

// ---------------------------------------------------------------------------
// degrees + normalized adjacencies
// ---------------------------------------------------------------------------
__global__ void k_deg(const float* __restrict__ adj){
    int v = blockIdx.x, tid = threadIdx.x;
    float s1 = 0.f, s2 = 0.f;
    for (int w = tid; w < 512; w += 256){
        s1 += adj[v*512 + w];
        s2 += adj[w*512 + v];
    }
    __shared__ float r1[256], r2[256];
    r1[tid] = s1; r2[tid] = s2;
    __syncthreads();
    for (int s = 128; s > 0; s >>= 1){
        if (tid < s){ r1[tid] += r1[tid+s]; r2[tid] += r2[tid+s]; }
        __syncthreads();
    }
    if (tid == 0){
        g_rd1[v] = rsqrtf(r1[0] + 1.f);
        g_rd2[v] = rsqrtf(r2[0] + 1.f);
    }
}

__global__ void k_norm(const float* __restrict__ adj){
    int w = blockIdx.x;
    float dw1 = g_rd1[w], dw2 = g_rd2[w];
    for (int v = threadIdx.x; v < 512; v += 256){
        float e = (v == w) ? 1.f : 0.f;
        g_An [w*512 + v] = g_rd1[v] * (adj[v*512 + w] + e) * dw1;
        g_AnT[w*512 + v] = g_rd2[v] * (adj[w*512 + v] + e) * dw2;
    }
}

// A' = M - diag(M) as plain bf16 [v][w]; d = diag(M) - 1 in fp32.
__global__ void k_prepA(){
    int v = blockIdx.x;
    for (int w = threadIdx.x; w < 512; w += 256){
        float a1 = g_An [w*512 + v];
        float a2 = g_AnT[w*512 + v];
        if (w == v){
            g_dA[v]       = a1 - 1.f;
            g_dA[512 + v] = a2 - 1.f;
            a1 = 0.f; a2 = 0.f;
        }
        g_Abf[0ULL*262144 + v*512 + w] = __float2bfloat16(a1);
        g_Abf[2ULL*262144 + v*512 + w] = __float2bfloat16(a2);
    }
}

// ---------------------------------------------------------------------------
// prep: pad inception weights to k=7 (windows end at l+6), build Horner W'_j,
// split everything to bf16 hi/lo in MMA-friendly layouts.
// ---------------------------------------------------------------------------
__global__ void k_prep(const float* i1w0,const float* i1b0,const float* i1w1,const float* i1b1,
                       const float* i1w2,const float* i1b2,const float* i1w3,const float* i1b3,
                       const float* i2w0,const float* i2b0,const float* i2w1,const float* i2b1,
                       const float* i2w2,const float* i2b2,const float* i2w3,const float* i2b3,
                       const float* m1w,const float* m1b,const float* m2w,const float* m2b){
    int g0 = blockIdx.x*256 + threadIdx.x, gstr = gridDim.x*256;
    const float* WS[8] = {i1w0,i1w1,i1w2,i1w3,i2w0,i2w1,i2w2,i2w3};
    const float* BS[8] = {i1b0,i1b1,i1b2,i1b3,i2b0,i2b1,i2b2,i2b3};
    const int KERN[4] = {2,3,6,7};

    // W7: [o][kd], kd = c*7 + tau
    for (int idx = g0; idx < 128*448; idx += gstr){
        int o = idx / 448, kd = idx - o*448;
        int c = kd / 7, tau = kd - c*7;
        int br = o >> 6, j = (o >> 4) & 3, oc = o & 15;
        int k = KERN[j];
        int t = tau - (7 - k);
        float v = (t >= 0) ? WS[br*4 + j][(oc*64 + c)*k + t] : 0.f;
        __nv_bfloat16 h = __float2bfloat16(v);
        g_W7h[idx] = h;
        g_W7l[idx] = __float2bfloat16(v - __bfloat162float(h));
    }
    for (int idx = g0; idx < 128; idx += gstr){
        int br = idx >> 6, j = (idx >> 4) & 3, oc = idx & 15;
        g_b7[idx] = BS[br*4 + j][oc];
    }
    for (int idx = g0; idx < 64; idx += gstr)
        g_bias[idx] = m1b[idx] + m2b[idx];

    const float COEF[5][5] = {
        {1.f, 1.f,      1.f,      1.f,      1.f     },
        {0.f, 1.f/3.f,  2.f/3.f,  1.f,      1.f     },
        {0.f, 0.f,      1.f/3.f,  1.f/3.f,  0.5f    },
        {0.f, 0.f,      0.f,      1.f/3.f,  1.f/6.f },
        {0.f, 0.f,      0.f,      0.f,      1.f/24.f}};
    // Wq bf16 stored [m][out=c][in=cp] so MMA A-fragment rows are outputs.
    for (int idx = g0; idx < 10*4096; idx += gstr){
        int m = idx >> 12, cp = (idx >> 6) & 63, c = idx & 63;
        int j = m % 5;
        const float* mw = (m < 5) ? m1w : m2w;
        float s = 0.f;
#pragma unroll
        for (int g = 0; g < 5; ++g)
            s += COEF[j][g] * mw[c*320 + g*64 + cp];
        __nv_bfloat16 h = __float2bfloat16(s);
        int widx = (m << 12) + (c << 6) + cp;   // [m][out][in]
        g_Wqh[widx] = h;
        g_Wql[widx] = __float2bfloat16(s - __bfloat162float(h));
    }
}

// ---------------------------------------------------------------------------
// FUSED inception + gate + qgen, all tensor-core (mma.sync split-bf16).
// ---------------------------------------------------------------------------
__global__ __launch_bounds__(128) void k_fused(const float* __restrict__ x){
    __shared__ __align__(16) char sm[38912];
    // stage-1 overlays
    __nv_bfloat16* sAh = (__nv_bfloat16*)(sm);            // [128][40]
    __nv_bfloat16* sAl = (__nv_bfloat16*)(sm + 10240);    // [128][40]
    __nv_bfloat16* sBh = (__nv_bfloat16*)(sm + 20480);    // [32][72]
    __nv_bfloat16* sBl = (__nv_bfloat16*)(sm + 25088);    // [32][72]
    // gate / stage-2 overlays
    float*         sG  = (float*)(sm);                    // [64][72] fp32
    __nv_bfloat16* sWh = (__nv_bfloat16*)(sm);            // [64][72]
    __nv_bfloat16* sWl = (__nv_bfloat16*)(sm + 9216);     // [64][72]
    __nv_bfloat16* sHh = (__nv_bfloat16*)(sm + 20480);    // [64][72]
    __nv_bfloat16* sHl = (__nv_bfloat16*)(sm + 29696);    // [64][72]

    int bn = blockIdx.x;
    int b = bn >> 9, n = bn & 511;
    int tid = threadIdx.x, lane = tid & 31, wid = tid >> 5;
    const float* xb = x + (u64)b*64*32768 + (u64)n*64;   // channel stride 512*64

    u32 uAh = smem_u32(sAh), uAl = smem_u32(sAl);
    u32 uBh = smem_u32(sBh), uBl = smem_u32(sBl);
    u32 uWh = smem_u32(sWh), uWl = smem_u32(sWl);
    u32 uHh = smem_u32(sHh), uHl = smem_u32(sHl);

    float acc[2][8][4];
#pragma unroll
    for (int m = 0; m < 2; ++m)
#pragma unroll
        for (int j = 0; j < 8; ++j)
#pragma unroll
            for (int e = 0; e < 4; ++e) acc[m][j][e] = 0.f;

    // ---------------- stage 1: inception GEMM (K = 448, 14 chunks of 32) ----
    for (int kc = 0; kc < 14; ++kc){
        int w0 = kc*32;
#pragma unroll
        for (int i = 0; i < 4; ++i){
            int idx = i*128 + tid;
            int row = idx >> 2, seg = idx & 3;
            *(uint4*)(sAh + row*40 + seg*8) = *(const uint4*)(g_W7h + row*448 + w0 + seg*8);
            *(uint4*)(sAl + row*40 + seg*8) = *(const uint4*)(g_W7l + row*448 + w0 + seg*8);
        }
        // B: im2col rows kd = w0+row, split fp32 -> bf16 hi/lo
#pragma unroll
        for (int i = 0; i < 8; ++i){
            int idx = i*128 + tid;          // (row, lpair): 32 x 32
            int row = idx >> 5, lp = idx & 31, l = lp*2;
            int kd = w0 + row;
            int c = kd / 7, tau = kd - c*7;
            int t = l + tau;
            float v0 = (t < 64) ? xb[(u64)c*32768 + t] : 0.f;
            float v1 = (t + 1 < 64) ? xb[(u64)c*32768 + t + 1] : 0.f;
            u32 h, lo; split2(v0, v1, h, lo);
            *(u32*)(sBh + row*72 + l) = h;
            *(u32*)(sBl + row*72 + l) = lo;
        }
        __syncthreads();
#pragma unroll
        for (int ks = 0; ks < 32; ks += 16){
            u32 ah[2][4], al[2][4];
            int arow = lane & 15, acol = ks + (lane >> 4)*8;
#pragma unroll
            for (int m = 0; m < 2; ++m){
                u32 ao = (u32)((wid*32 + m*16 + arow)*40 + acol)*2;
                ldmA(ah[m], uAh + ao);
                ldmA(al[m], uAl + ao);
            }
            int brow = ks + (lane & 15), bcol = (lane >> 4)*8;
#pragma unroll
            for (int g = 0; g < 4; ++g){
                u32 bh[4], bl[4];
                u32 bo = (u32)(brow*72 + g*16 + bcol)*2;
                ldmBT(bh, uBh + bo);
                ldmBT(bl, uBl + bo);
#pragma unroll
                for (int m = 0; m < 2; ++m){
#pragma unroll
                    for (int h = 0; h < 2; ++h){
                        float* c = acc[m][g*2 + h];
                        mma16816(c, ah[m], bh[2*h], bh[2*h+1]);
                        mma16816(c, ah[m], bl[2*h], bl[2*h+1]);
                        mma16816(c, al[m], bh[2*h], bh[2*h+1]);
                    }
                }
            }
        }
        __syncthreads();
    }

    // ---------------- gate: h = tanh(filt) * sigmoid(gate) ------------------
    int lbase = (lane & 3)*2, rbase = lane >> 2;
    if (wid >= 2){   // gate rows: o = 64..127 -> write sigmoid to sG
#pragma unroll
        for (int m = 0; m < 2; ++m){
            int o = wid*32 + m*16 + rbase;
#pragma unroll
            for (int jj = 0; jj < 8; ++jj){
                int l = jj*8 + lbase;
                float* c = acc[m][jj];
                float b0 = g_b7[o], b1 = g_b7[o + 8];
                float2 g0, g1;
                g0.x = 1.f/(1.f + expf(-(c[0] + b0)));
                g0.y = 1.f/(1.f + expf(-(c[1] + b0)));
                g1.x = 1.f/(1.f + expf(-(c[2] + b1)));
                g1.y = 1.f/(1.f + expf(-(c[3] + b1)));
                *(float2*)(sG + (o - 64)*72 + l) = g0;
                *(float2*)(sG + (o - 64 + 8)*72 + l) = g1;
            }
        }
    }
    __syncthreads();
    if (wid < 2){    // filt rows: o = c = 0..63 -> h split to sHh/sHl
#pragma unroll
        for (int m = 0; m < 2; ++m){
            int c0 = wid*32 + m*16 + rbase;
#pragma unroll
            for (int jj = 0; jj < 8; ++jj){
                int l = jj*8 + lbase;
                float* c = acc[m][jj];
                float b0 = g_b7[c0], b1 = g_b7[c0 + 8];
                float2 ga = *(const float2*)(sG + c0*72 + l);
                float2 gb = *(const float2*)(sG + (c0 + 8)*72 + l);
                float h0 = tanhf(c[0] + b0) * ga.x;
                float h1 = tanhf(c[1] + b0) * ga.y;
                float h2 = tanhf(c[2] + b1) * gb.x;
                float h3 = tanhf(c[3] + b1) * gb.y;
                u32 ph0, pl0, ph1, pl1;
                split2(h0, h1, ph0, pl0);
                split2(h2, h3, ph1, pl1);
                *(u32*)(sHh + c0*72 + l) = ph0;
                *(u32*)(sHl + c0*72 + l) = pl0;
                *(u32*)(sHh + (c0 + 8)*72 + l) = ph1;
                *(u32*)(sHl + (c0 + 8)*72 + l) = pl1;
            }
        }
    }

    // ---------------- stage 2: q_m = W'_m @ h, m = 0..9 ---------------------
    for (int m = 0; m < 10; ++m){
        __syncthreads();   // sH visible (first iter); sW safe to overwrite
#pragma unroll
        for (int i = 0; i < 4; ++i){
            int idx = i*128 + tid;
            int row = idx >> 3, seg = idx & 7;
            *(uint4*)(sWh + row*72 + seg*8) = *(const uint4*)(g_Wqh + m*4096 + row*64 + seg*8);
            *(uint4*)(sWl + row*72 + seg*8) = *(const uint4*)(g_Wql + m*4096 + row*64 + seg*8);
        }
        __syncthreads();

        float a2[8][4];
#pragma unroll
        for (int j = 0; j < 8; ++j)
#pragma unroll
            for (int e = 0; e < 4; ++e) a2[j][e] = 0.f;

#pragma unroll
        for (int ks = 0; ks < 64; ks += 16){
            u32 ah[4], al[4];
            u32 ao = (u32)((wid*16 + (lane & 15))*72 + ks + (lane >> 4)*8)*2;
            ldmA(ah, uWh + ao);
            ldmA(al, uWl + ao);
            int brow = ks + (lane & 15), bcol = (lane >> 4)*8;
#pragma unroll
            for (int g = 0; g < 4; ++g){
                u32 bh[4], bl[4];
                u32 bo = (u32)(brow*72 + g*16 + bcol)*2;
                ldmBT(bh, uHh + bo);
                ldmBT(bl, uHl + bo);
#pragma unroll
                for (int h = 0; h < 2; ++h){
                    float* c = a2[g*2 + h];
                    mma16816(c, ah, bh[2*h], bh[2*h+1]);
                    mma16816(c, ah, bl[2*h], bl[2*h+1]);
                    mma16816(c, al, bh[2*h], bh[2*h+1]);
                }
            }
        }

        // epilogue for q_m
        int cp = wid*16 + rbase;
        u64 eoff0 = ((u64)(b*64 + cp)*512 + n)*64;
        u64 eoff1 = ((u64)(b*64 + cp + 8)*512 + n)*64;
        if (m == 4 || m == 9){
            __nv_bfloat16* wh = g_bf + (u64)(m == 4 ? 0 : 6)*BUFSZ;
            __nv_bfloat16* wl = wh + BUFSZ;
#pragma unroll
            for (int jj = 0; jj < 8; ++jj){
                int l = jj*8 + lbase;
                float* c = a2[jj];
                u32 h0, l0, h1, l1;
                split2(c[0], c[1], h0, l0);
                split2(c[2], c[3], h1, l1);
                *(u32*)(wh + eoff0 + l) = h0;
                *(u32*)(wl + eoff0 + l) = l0;
                *(u32*)(wh + eoff1 + l) = h1;
                *(u32*)(wl + eoff1 + l) = l1;
            }
        } else {
            float* dst = g_pool + (u64)m*BUFSZ;
#pragma unroll
            for (int jj = 0; jj < 8; ++jj){
                int l = jj*8 + lbase;
                float* c = a2[jj];
                *(float2*)(dst + eoff0 + l) = make_float2(c[0], c[1]);
                *(float2*)(dst + eoff1 + l) = make_float2(c[2], c[3]);
            }
        }
    }
}

// ---------------------------------------------------------------------------
// tensor-core (mma.sync) Horner node step: r' = q + d∘r + A'·r
// 512 threads, CTA tile 256v x 128l; warp (wy=wid&7, wx=wid>>3): 32v x 64l.
// XOR-swizzled conflict-free smem:
//   A: 256 rows x 64B, phys-unit = seg ^ ((row>>1)&3)
//   B: 32 rows x 256B (hi, lo), phys-unit = seg ^ (row&7)
// Stage = 32768B: [A 16384][Bh 8192][Bl 8192]; 2-stage cp.async pipeline.
// blockIdx.z selects branch: asel+=z, qid+=5z, bslot+=6z, wslot+=6z.
// MODE 0: write r' as bf16 hi/lo.
// MODE 3: z==0 -> fp32 ACC;  z==1 -> out[l+6] = r' + q + bias (no ACC read).
// ---------------------------------------------------------------------------
#define NODE_SST 32768
#define NODE_SMEM (2*NODE_SST)

__device__ __forceinline__ void node_prefetch(
    u32 sb, const __nv_bfloat16* Ah,
    const __nv_bfloat16* Bh0, const __nv_bfloat16* Bl0,
    int w0, int v0c, int tid){
    // A: 256 rows x 4 segs, swizzled
#pragma unroll
    for (int i = 0; i < 2; ++i){
        int idx = i*512 + tid;              // 0..1023
        int row = idx >> 2, seg = idx & 3;
        u64 goff = (u64)(v0c + row)*512 + w0 + seg*8;
        cpa16(sb + row*64 + ((seg ^ ((row >> 1) & 3)) << 4), Ah + goff);
    }
    // B: 32 rows x 16 segs (segs 0..7 -> bc0, 8..15 -> bc1), swizzled
    {
        int row = tid >> 4, seg = tid & 15; // 512 = 32*16
        u64 goff = (u64)(seg >> 3)*32768 + (u64)(w0 + row)*64 + (seg & 7)*8;
        u32 d = sb + 16384 + row*256 + ((seg ^ (row & 7)) << 4);
        cpa16(d, Bh0 + goff);
        cpa16(d + 8192, Bl0 + goff);
    }
}

template<int MODE>
__global__ __launch_bounds__(512, 1)
void k_node_mma(int asel, int qid, int bslot, int wslot, float* __restrict__ outp){
    extern __shared__ __align__(16) char smn[];
    u32 base = smem_u32(smn);

    int z = blockIdx.z;
    asel += z; qid += 5*z; bslot += 6*z; wslot += 6*z;

    int tid = threadIdx.x, lane = tid & 31, wid = tid >> 5;
    int wy = wid & 7, wx = wid >> 3;
    int bc0 = blockIdx.x*2, v0c = blockIdx.y << 8;

    const __nv_bfloat16* Ah = g_Abf + (u64)(asel*2)*262144;
    const __nv_bfloat16* Bh0 = g_bf + (u64)bslot*BUFSZ + (u64)bc0*32768;
    const __nv_bfloat16* Bl0 = g_bf + (u64)(bslot+1)*BUFSZ + (u64)bc0*32768;
    const float* dvec = g_dA + asel*512;

    float acc[2][8][4];
#pragma unroll
    for (int m = 0; m < 2; ++m)
#pragma unroll
        for (int j = 0; j < 8; ++j)
#pragma unroll
            for (int e = 0; e < 4; ++e) acc[m][j][e] = 0.f;

    // lane-constant swizzle terms
    int arow = lane & 15;
    int sA = (arow >> 1) & 3;          // A swizzle (row>>1)&3 within 16-row tile
    int sB = lane & 7;                 // B swizzle (brow&7) == lane&7
    int cB = lane >> 4;

    // prologue: prefetch chunk 0
    node_prefetch(base, Ah, Bh0, Bl0, 0, v0c, tid);
    cpa_commit();

    for (int kc = 0; kc < 16; ++kc){
        if (kc < 15){
            node_prefetch(base + ((kc+1)&1)*NODE_SST, Ah, Bh0, Bl0,
                          (kc+1)*32, v0c, tid);
            cpa_commit();
            cpa_wait<1>();
        } else {
            cpa_wait<0>();
        }
        __syncthreads();

        u32 sb = base + (kc&1)*NODE_SST;
        u32 uA = sb, uBh = sb + 16384, uBl = sb + 24576;
#pragma unroll
        for (int ks = 0; ks < 32; ks += 16){
            u32 ah[2][4];
            int ucol = (ks >> 3) + (lane >> 4);
#pragma unroll
            for (int m = 0; m < 2; ++m){
                int row = wy*32 + m*16 + arow;
                u32 ao = (u32)(row*64 + ((ucol ^ sA) << 4));
                ldmA(ah[m], uA + ao);
            }
            int brow = ks + (lane & 15);
#pragma unroll
            for (int g = 0; g < 4; ++g){
                u32 bh[4], bl[4];
                int u = ((wx*4 + g) << 1) + cB;
                u32 bo = (u32)(brow*256 + ((u ^ sB) << 4));
                ldmBT(bh, uBh + bo);
                ldmBT(bl, uBl + bo);
#pragma unroll
                for (int m = 0; m < 2; ++m){
#pragma unroll
                    for (int h = 0; h < 2; ++h){
                        float* c = acc[m][g*2 + h];
                        mma16816(c, ah[m], bh[2*h], bh[2*h+1]);
                        mma16816(c, ah[m], bl[2*h], bl[2*h+1]);
                    }
                }
            }
        }
        __syncthreads();   // all reads of stage kc done before it is overwritten
    }

    int lbase = (lane & 3)*2, rbase = lane >> 2;
#pragma unroll
    for (int m = 0; m < 2; ++m){
        int v = v0c + wy*32 + m*16 + rbase;
        float d0 = dvec[v], d1 = dvec[v + 8];
#pragma unroll
        for (int jj = 0; jj < 8; ++jj){
            int nloc = wx*64 + jj*8 + lbase;       // 0..127
            int bcl = bc0 + (nloc >> 6);
            int l = nloc & 63;
            float* c = acc[m][jj];
            const float* qp = g_pool + (u64)qid*BUFSZ + (u64)bcl*32768;
            float2 q0 = *(const float2*)(qp + (u64)v*64 + l);
            float2 q1 = *(const float2*)(qp + (u64)(v+8)*64 + l);
            // reconstruct r (17-bit) for the exact diagonal path
            const __nv_bfloat16* rhp = g_bf + (u64)bslot*BUFSZ + (u64)bcl*32768;
            const __nv_bfloat16* rlp = rhp + BUFSZ;
            float2 r0h = bf2f2(*(const u32*)(rhp + (u64)v*64 + l));
            float2 r0l = bf2f2(*(const u32*)(rlp + (u64)v*64 + l));
            float2 r1h = bf2f2(*(const u32*)(rhp + (u64)(v+8)*64 + l));
            float2 r1l = bf2f2(*(const u32*)(rlp + (u64)(v+8)*64 + l));
            float a0 = c[0] + q0.x + d0*(r0h.x + r0l.x);
            float a1 = c[1] + q0.y + d0*(r0h.y + r0l.y);
            float a2 = c[2] + q1.x + d1*(r1h.x + r1l.x);
            float a3 = c[3] + q1.y + d1*(r1h.y + r1l.y);
            if (MODE == 0){
                __nv_bfloat16* wh = g_bf + (u64)wslot*BUFSZ + (u64)bcl*32768;
                __nv_bfloat16* wl = wh + BUFSZ;
                u32 h0, l0, h1, l1;
                split2(a0, a1, h0, l0);
                split2(a2, a3, h1, l1);
                *(u32*)(wh + (u64)v*64 + l) = h0;
                *(u32*)(wl + (u64)v*64 + l) = l0;
                *(u32*)(wh + (u64)(v+8)*64 + l) = h1;
                *(u32*)(wl + (u64)(v+8)*64 + l) = l1;
            } else {   // MODE 3
                if (z == 0){
                    float* op = g_pool + 12ULL*BUFSZ + (u64)bcl*32768;
                    *(float2*)(op + (u64)v*64 + l) = make_float2(a0, a1);
                    *(float2*)(op + (u64)(v+8)*64 + l) = make_float2(a2, a3);
                } else {
                    float bia = g_bias[bcl & 63];
                    float* op = outp + (u64)bcl*32768;
                    a0 += bia; a1 += bia; a2 += bia; a3 += bia;
                    if (l < 58)     op[(u64)v*64 + l + 6]       = a0;
                    if (l + 1 < 58) op[(u64)v*64 + l + 7]       = a1;
                    if (l < 58)     op[(u64)(v+8)*64 + l + 6]   = a2;
                    if (l + 1 < 58) op[(u64)(v+8)*64 + l + 7]   = a3;
                }
            }
        }
    }
}

// out[..., l+6] += ACC[..., l]  (l < 58)
__global__ void k_finaladd(float* __restrict__ outp){
    u64 i = (u64)blockIdx.x*256 + threadIdx.x;   // 65536*256 = 16.8M
    int l = (int)(i & 63);
    if (l < 58){
        u64 row = i >> 6;
        outp[row*64 + l + 6] += g_pool[12ULL*BUFSZ + i];
    }
}

__global__ void k_zeropad(float* __restrict__ outp){
    int i = blockIdx.x*256 + threadIdx.x;
    if (i < 8*64*512*6){
        int row = i / 6, t = i - row*6;
        outp[(u64)row*64 + t] = 0.f;
    }
}

// ---------------------------------------------------------------------------
extern "C" void kernel_launch(void* const* d_in, const int* in_sizes, int n_in,
                              void* d_out, int out_size){
    (void)in_sizes; (void)n_in; (void)out_size;
    const float* x   = (const float*)d_in[0];
    const float* adj = (const float*)d_in[1];
    float* out = (float*)d_out;

    // allow >48KB dynamic smem for the node kernels (idempotent)
    cudaFuncSetAttribute(k_node_mma<0>, cudaFuncAttributeMaxDynamicSharedMemorySize, NODE_SMEM);
    cudaFuncSetAttribute(k_node_mma<3>, cudaFuncAttributeMaxDynamicSharedMemorySize, NODE_SMEM);

    k_deg  <<<512, 256>>>(adj);
    k_norm <<<512, 256>>>(adj);
    k_prepA<<<512, 256>>>();
    k_prep<<<64, 256>>>(
        (const float*)d_in[ 2], (const float*)d_in[ 3], (const float*)d_in[ 4], (const float*)d_in[ 5],
        (const float*)d_in[ 6], (const float*)d_in[ 7], (const float*)d_in[ 8], (const float*)d_in[ 9],
        (const float*)d_in[10], (const float*)d_in[11], (const float*)d_in[12], (const float*)d_in[13],
        (const float*)d_in[14], (const float*)d_in[15], (const float*)d_in[16], (const float*)d_in[17],
        (const float*)d_in[18], (const float*)d_in[19], (const float*)d_in[20], (const float*)d_in[21]);

    k_fused<<<4096, 128>>>(x);

    // Horner: branch0 seed slot 0 (q4), branch1 seed slot 6 (q9);
    // all launches run both branches via gridDim.z = 2.
    dim3 ng3(256, 2, 2);
    k_node_mma<0><<<ng3, 512, NODE_SMEM>>>(0, 3, 0, 2, nullptr);   // step 0
    k_node_mma<0><<<ng3, 512, NODE_SMEM>>>(0, 2, 2, 4, nullptr);   // step 1
    k_node_mma<0><<<ng3, 512, NODE_SMEM>>>(0, 1, 4, 2, nullptr);   // step 2
    k_node_mma<3><<<ng3, 512, NODE_SMEM>>>(0, 0, 2, 0, out);       // finals (both)
    k_finaladd<<<65536, 256>>>(out);
    k_zeropad<<<6144, 256>>>(out);
}

// round 13
// speedup vs baseline: 1.0304x; 1.0304x over previous
#include <cuda_runtime.h>
#include <cuda_bf16.h>

typedef unsigned long long u64;
typedef unsigned int u32;

// ---------------------------------------------------------------------------
// Shapes: B=8, C=64, N=512, T=64, valid L=58 (stored padded to 64).
// fp32 pool: q0..q9 (ids 0-9; 4 and 9 unused as fp32), ACC=12.
// bf16 pool slots (BUFSZ each):
//   0/1 seed1(q4) hi/lo, 2/3 & 4/5 branch0 ping-pong,
//   6/7 seed2(q9) hi/lo, 8/9 & 10/11 branch1 ping-pong.
// Node step: r' = q + d∘r + A'·r  with d = diag(M)-1 (fp32, epilogue) and
// A' = M - diag(M) (tiny entries ~4e-3, plain bf16, 2 MMA products).
// ---------------------------------------------------------------------------
#define BUFSZ (8ULL*64ULL*512ULL*64ULL)

__device__ float g_pool[13ULL*BUFSZ];
__device__ __nv_bfloat16 g_bf[12ULL*BUFSZ];
__device__ __nv_bfloat16 g_Abf[4ULL*512*512];  // slots 0,2 used: [asel*2][v][w] of A'
__device__ float g_dA[2*512];                  // diag(M)-1 per branch

__device__ float g_An [512*512];   // [w][v] = M1[v][w]
__device__ float g_AnT[512*512];   // [w][v] = M2[v][w]
__device__ float g_rd1[512], g_rd2[512];
__device__ __nv_bfloat16 g_W7h[128*448];   // [o][kd] hi
__device__ __nv_bfloat16 g_W7l[128*448];   // [o][kd] lo
__device__ float g_b7[128];
__device__ __nv_bfloat16 g_Wqh[10*64*64];  // [m][out][in] hi  (MMA A-row = out)
__device__ __nv_bfloat16 g_Wql[10*64*64];  // [m][out][in] lo
__device__ float g_bias[64];

// ---------------------------------------------------------------------------
// helpers
// ---------------------------------------------------------------------------
__device__ __forceinline__ u32 smem_u32(const void* p){
    u32 a;
    asm("{ .reg .u64 t; cvta.to.shared.u64 t, %1; cvt.u32.u64 %0, t; }" : "=r"(a) : "l"(p));
    return a;
}
// split a pair of fp32 into packed bf16 hi / bf16 lo
__device__ __forceinline__ void split2(float a0, float a1, u32& hi, u32& lo){
    __nv_bfloat16 h0 = __float2bfloat16(a0);
    __nv_bfloat16 h1 = __float2bfloat16(a1);
    float r0 = a0 - __bfloat162float(h0);
    float r1 = a1 - __bfloat162float(h1);
    union { __nv_bfloat162 v; u32 u; } ch, cl;
    ch.v = __halves2bfloat162(h0, h1);
    cl.v = __halves2bfloat162(__float2bfloat16(r0), __float2bfloat16(r1));
    hi = ch.u; lo = cl.u;
}
__device__ __forceinline__ float2 bf2f2(u32 u){
    union { u32 u; __nv_bfloat162 v; } c; c.u = u;
    return __bfloat1622float2(c.v);
}

// ---------------------------------------------------------------------------
// mma.sync / ldmatrix / cp.async wrappers (baseline PTX, legal on compute_103)
// ---------------------------------------------------------------------------
__device__ __forceinline__ void mma16816(float* c, const u32* a, u32 b0, u32 b1){
    asm volatile(
        "mma.sync.aligned.m16n8k16.row.col.f32.bf16.bf16.f32 "
        "{%0,%1,%2,%3}, {%4,%5,%6,%7}, {%8,%9}, {%0,%1,%2,%3};"
        : "+f"(c[0]), "+f"(c[1]), "+f"(c[2]), "+f"(c[3])
        : "r"(a[0]), "r"(a[1]), "r"(a[2]), "r"(a[3]), "r"(b0), "r"(b1));
}
__device__ __forceinline__ void ldmA(u32* r, u32 addr){
    asm volatile("ldmatrix.sync.aligned.m8n8.x4.shared.b16 {%0,%1,%2,%3}, [%4];"
        : "=r"(r[0]), "=r"(r[1]), "=r"(r[2]), "=r"(r[3]) : "r"(addr));
}
__device__ __forceinline__ void ldmBT(u32* r, u32 addr){
    asm volatile("ldmatrix.sync.aligned.m8n8.x4.trans.shared.b16 {%0,%1,%2,%3}, [%4];"
        : "=r"(r[0]), "=r"(r[1]), "=r"(r[2]), "=r"(r[3]) : "r"(addr));
}
__device__ __forceinline__ void cpa16(u32 dst, const void* src){
    asm volatile("cp.async.cg.shared.global [%0], [%1], 16;" :: "r"(dst), "l"(src));
}
__device__ __forceinline__ void cpa_commit(){
    asm volatile("cp.async.commit_group;" ::: "memory");
}
template<int N>
__device__ __forceinline__ void cpa_wait(){
    asm volatile("cp.async.wait_group %0;" :: "n"(N) : "memory");
}

// ---------------------------------------------------------------------------
// degrees + normalized adjacencies
// ---------------------------------------------------------------------------
__global__ void k_deg(const float* __restrict__ adj){
    int v = blockIdx.x, tid = threadIdx.x;
    float s1 = 0.f, s2 = 0.f;
    for (int w = tid; w < 512; w += 256){
        s1 += adj[v*512 + w];
        s2 += adj[w*512 + v];
    }
    __shared__ float r1[256], r2[256];
    r1[tid] = s1; r2[tid] = s2;
    __syncthreads();
    for (int s = 128; s > 0; s >>= 1){
        if (tid < s){ r1[tid] += r1[tid+s]; r2[tid] += r2[tid+s]; }
        __syncthreads();
    }
    if (tid == 0){
        g_rd1[v] = rsqrtf(r1[0] + 1.f);
        g_rd2[v] = rsqrtf(r2[0] + 1.f);
    }
}

__global__ void k_norm(const float* __restrict__ adj){
    int w = blockIdx.x;
    float dw1 = g_rd1[w], dw2 = g_rd2[w];
    for (int v = threadIdx.x; v < 512; v += 256){
        float e = (v == w) ? 1.f : 0.f;
        g_An [w*512 + v] = g_rd1[v] * (adj[v*512 + w] + e) * dw1;
        g_AnT[w*512 + v] = g_rd2[v] * (adj[w*512 + v] + e) * dw2;
    }
}

// A' = M - diag(M) as plain bf16 [v][w]; d = diag(M) - 1 in fp32.
__global__ void k_prepA(){
    int v = blockIdx.x;
    for (int w = threadIdx.x; w < 512; w += 256){
        float a1 = g_An [w*512 + v];
        float a2 = g_AnT[w*512 + v];
        if (w == v){
            g_dA[v]       = a1 - 1.f;
            g_dA[512 + v] = a2 - 1.f;
            a1 = 0.f; a2 = 0.f;
        }
        g_Abf[0ULL*262144 + v*512 + w] = __float2bfloat16(a1);
        g_Abf[2ULL*262144 + v*512 + w] = __float2bfloat16(a2);
    }
}

// ---------------------------------------------------------------------------
// prep: pad inception weights to k=7 (windows end at l+6), build Horner W'_j,
// split everything to bf16 hi/lo in MMA-friendly layouts.
// ---------------------------------------------------------------------------
__global__ void k_prep(const float* i1w0,const float* i1b0,const float* i1w1,const float* i1b1,
                       const float* i1w2,const float* i1b2,const float* i1w3,const float* i1b3,
                       const float* i2w0,const float* i2b0,const float* i2w1,const float* i2b1,
                       const float* i2w2,const float* i2b2,const float* i2w3,const float* i2b3,
                       const float* m1w,const float* m1b,const float* m2w,const float* m2b){
    int g0 = blockIdx.x*256 + threadIdx.x, gstr = gridDim.x*256;
    const float* WS[8] = {i1w0,i1w1,i1w2,i1w3,i2w0,i2w1,i2w2,i2w3};
    const float* BS[8] = {i1b0,i1b1,i1b2,i1b3,i2b0,i2b1,i2b2,i2b3};
    const int KERN[4] = {2,3,6,7};

    // W7: [o][kd], kd = c*7 + tau
    for (int idx = g0; idx < 128*448; idx += gstr){
        int o = idx / 448, kd = idx - o*448;
        int c = kd / 7, tau = kd - c*7;
        int br = o >> 6, j = (o >> 4) & 3, oc = o & 15;
        int k = KERN[j];
        int t = tau - (7 - k);
        float v = (t >= 0) ? WS[br*4 + j][(oc*64 + c)*k + t] : 0.f;
        __nv_bfloat16 h = __float2bfloat16(v);
        g_W7h[idx] = h;
        g_W7l[idx] = __float2bfloat16(v - __bfloat162float(h));
    }
    for (int idx = g0; idx < 128; idx += gstr){
        int br = idx >> 6, j = (idx >> 4) & 3, oc = idx & 15;
        g_b7[idx] = BS[br*4 + j][oc];
    }
    for (int idx = g0; idx < 64; idx += gstr)
        g_bias[idx] = m1b[idx] + m2b[idx];

    const float COEF[5][5] = {
        {1.f, 1.f,      1.f,      1.f,      1.f     },
        {0.f, 1.f/3.f,  2.f/3.f,  1.f,      1.f     },
        {0.f, 0.f,      1.f/3.f,  1.f/3.f,  0.5f    },
        {0.f, 0.f,      0.f,      1.f/3.f,  1.f/6.f },
        {0.f, 0.f,      0.f,      0.f,      1.f/24.f}};
    // Wq bf16 stored [m][out=c][in=cp] so MMA A-fragment rows are outputs.
    for (int idx = g0; idx < 10*4096; idx += gstr){
        int m = idx >> 12, cp = (idx >> 6) & 63, c = idx & 63;
        int j = m % 5;
        const float* mw = (m < 5) ? m1w : m2w;
        float s = 0.f;
#pragma unroll
        for (int g = 0; g < 5; ++g)
            s += COEF[j][g] * mw[c*320 + g*64 + cp];
        __nv_bfloat16 h = __float2bfloat16(s);
        int widx = (m << 12) + (c << 6) + cp;   // [m][out][in]
        g_Wqh[widx] = h;
        g_Wql[widx] = __float2bfloat16(s - __bfloat162float(h));
    }
}

// ---------------------------------------------------------------------------
// FUSED inception + gate + qgen, all tensor-core (mma.sync split-bf16).
// ---------------------------------------------------------------------------
__global__ __launch_bounds__(128) void k_fused(const float* __restrict__ x){
    __shared__ __align__(16) char sm[38912];
    // stage-1 overlays
    __nv_bfloat16* sAh = (__nv_bfloat16*)(sm);            // [128][40]
    __nv_bfloat16* sAl = (__nv_bfloat16*)(sm + 10240);    // [128][40]
    __nv_bfloat16* sBh = (__nv_bfloat16*)(sm + 20480);    // [32][72]
    __nv_bfloat16* sBl = (__nv_bfloat16*)(sm + 25088);    // [32][72]
    // gate / stage-2 overlays
    float*         sG  = (float*)(sm);                    // [64][72] fp32
    __nv_bfloat16* sWh = (__nv_bfloat16*)(sm);            // [64][72]
    __nv_bfloat16* sWl = (__nv_bfloat16*)(sm + 9216);     // [64][72]
    __nv_bfloat16* sHh = (__nv_bfloat16*)(sm + 20480);    // [64][72]
    __nv_bfloat16* sHl = (__nv_bfloat16*)(sm + 29696);    // [64][72]

    int bn = blockIdx.x;
    int b = bn >> 9, n = bn & 511;
    int tid = threadIdx.x, lane = tid & 31, wid = tid >> 5;
    const float* xb = x + (u64)b*64*32768 + (u64)n*64;   // channel stride 512*64

    u32 uAh = smem_u32(sAh), uAl = smem_u32(sAl);
    u32 uBh = smem_u32(sBh), uBl = smem_u32(sBl);
    u32 uWh = smem_u32(sWh), uWl = smem_u32(sWl);
    u32 uHh = smem_u32(sHh), uHl = smem_u32(sHl);

    float acc[2][8][4];
#pragma unroll
    for (int m = 0; m < 2; ++m)
#pragma unroll
        for (int j = 0; j < 8; ++j)
#pragma unroll
            for (int e = 0; e < 4; ++e) acc[m][j][e] = 0.f;

    // ---------------- stage 1: inception GEMM (K = 448, 14 chunks of 32) ----
    for (int kc = 0; kc < 14; ++kc){
        int w0 = kc*32;
#pragma unroll
        for (int i = 0; i < 4; ++i){
            int idx = i*128 + tid;
            int row = idx >> 2, seg = idx & 3;
            *(uint4*)(sAh + row*40 + seg*8) = *(const uint4*)(g_W7h + row*448 + w0 + seg*8);
            *(uint4*)(sAl + row*40 + seg*8) = *(const uint4*)(g_W7l + row*448 + w0 + seg*8);
        }
        // B: im2col rows kd = w0+row, split fp32 -> bf16 hi/lo
#pragma unroll
        for (int i = 0; i < 8; ++i){
            int idx = i*128 + tid;          // (row, lpair): 32 x 32
            int row = idx >> 5, lp = idx & 31, l = lp*2;
            int kd = w0 + row;
            int c = kd / 7, tau = kd - c*7;
            int t = l + tau;
            float v0 = (t < 64) ? xb[(u64)c*32768 + t] : 0.f;
            float v1 = (t + 1 < 64) ? xb[(u64)c*32768 + t + 1] : 0.f;
            u32 h, lo; split2(v0, v1, h, lo);
            *(u32*)(sBh + row*72 + l) = h;
            *(u32*)(sBl + row*72 + l) = lo;
        }
        __syncthreads();
#pragma unroll
        for (int ks = 0; ks < 32; ks += 16){
            u32 ah[2][4], al[2][4];
            int arow = lane & 15, acol = ks + (lane >> 4)*8;
#pragma unroll
            for (int m = 0; m < 2; ++m){
                u32 ao = (u32)((wid*32 + m*16 + arow)*40 + acol)*2;
                ldmA(ah[m], uAh + ao);
                ldmA(al[m], uAl + ao);
            }
            int brow = ks + (lane & 15), bcol = (lane >> 4)*8;
#pragma unroll
            for (int g = 0; g < 4; ++g){
                u32 bh[4], bl[4];
                u32 bo = (u32)(brow*72 + g*16 + bcol)*2;
                ldmBT(bh, uBh + bo);
                ldmBT(bl, uBl + bo);
#pragma unroll
                for (int m = 0; m < 2; ++m){
#pragma unroll
                    for (int h = 0; h < 2; ++h){
                        float* c = acc[m][g*2 + h];
                        mma16816(c, ah[m], bh[2*h], bh[2*h+1]);
                        mma16816(c, ah[m], bl[2*h], bl[2*h+1]);
                        mma16816(c, al[m], bh[2*h], bh[2*h+1]);
                    }
                }
            }
        }
        __syncthreads();
    }

    // ---------------- gate: h = tanh(filt) * sigmoid(gate) ------------------
    int lbase = (lane & 3)*2, rbase = lane >> 2;
    if (wid >= 2){   // gate rows: o = 64..127 -> write sigmoid to sG
#pragma unroll
        for (int m = 0; m < 2; ++m){
            int o = wid*32 + m*16 + rbase;
#pragma unroll
            for (int jj = 0; jj < 8; ++jj){
                int l = jj*8 + lbase;
                float* c = acc[m][jj];
                float b0 = g_b7[o], b1 = g_b7[o + 8];
                float2 g0, g1;
                g0.x = 1.f/(1.f + expf(-(c[0] + b0)));
                g0.y = 1.f/(1.f + expf(-(c[1] + b0)));
                g1.x = 1.f/(1.f + expf(-(c[2] + b1)));
                g1.y = 1.f/(1.f + expf(-(c[3] + b1)));
                *(float2*)(sG + (o - 64)*72 + l) = g0;
                *(float2*)(sG + (o - 64 + 8)*72 + l) = g1;
            }
        }
    }
    __syncthreads();
    if (wid < 2){    // filt rows: o = c = 0..63 -> h split to sHh/sHl
#pragma unroll
        for (int m = 0; m < 2; ++m){
            int c0 = wid*32 + m*16 + rbase;
#pragma unroll
            for (int jj = 0; jj < 8; ++jj){
                int l = jj*8 + lbase;
                float* c = acc[m][jj];
                float b0 = g_b7[c0], b1 = g_b7[c0 + 8];
                float2 ga = *(const float2*)(sG + c0*72 + l);
                float2 gb = *(const float2*)(sG + (c0 + 8)*72 + l);
                float h0 = tanhf(c[0] + b0) * ga.x;
                float h1 = tanhf(c[1] + b0) * ga.y;
                float h2 = tanhf(c[2] + b1) * gb.x;
                float h3 = tanhf(c[3] + b1) * gb.y;
                u32 ph0, pl0, ph1, pl1;
                split2(h0, h1, ph0, pl0);
                split2(h2, h3, ph1, pl1);
                *(u32*)(sHh + c0*72 + l) = ph0;
                *(u32*)(sHl + c0*72 + l) = pl0;
                *(u32*)(sHh + (c0 + 8)*72 + l) = ph1;
                *(u32*)(sHl + (c0 + 8)*72 + l) = pl1;
            }
        }
    }

    // ---------------- stage 2: q_m = W'_m @ h, m = 0..9 ---------------------
    for (int m = 0; m < 10; ++m){
        __syncthreads();   // sH visible (first iter); sW safe to overwrite
#pragma unroll
        for (int i = 0; i < 4; ++i){
            int idx = i*128 + tid;
            int row = idx >> 3, seg = idx & 7;
            *(uint4*)(sWh + row*72 + seg*8) = *(const uint4*)(g_Wqh + m*4096 + row*64 + seg*8);
            *(uint4*)(sWl + row*72 + seg*8) = *(const uint4*)(g_Wql + m*4096 + row*64 + seg*8);
        }
        __syncthreads();

        float a2[8][4];
#pragma unroll
        for (int j = 0; j < 8; ++j)
#pragma unroll
            for (int e = 0; e < 4; ++e) a2[j][e] = 0.f;

#pragma unroll
        for (int ks = 0; ks < 64; ks += 16){
            u32 ah[4], al[4];
            u32 ao = (u32)((wid*16 + (lane & 15))*72 + ks + (lane >> 4)*8)*2;
            ldmA(ah, uWh + ao);
            ldmA(al, uWl + ao);
            int brow = ks + (lane & 15), bcol = (lane >> 4)*8;
#pragma unroll
            for (int g = 0; g < 4; ++g){
                u32 bh[4], bl[4];
                u32 bo = (u32)(brow*72 + g*16 + bcol)*2;
                ldmBT(bh, uHh + bo);
                ldmBT(bl, uHl + bo);
#pragma unroll
                for (int h = 0; h < 2; ++h){
                    float* c = a2[g*2 + h];
                    mma16816(c, ah, bh[2*h], bh[2*h+1]);
                    mma16816(c, ah, bl[2*h], bl[2*h+1]);
                    mma16816(c, al, bh[2*h], bh[2*h+1]);
                }
            }
        }

        // epilogue for q_m
        int cp = wid*16 + rbase;
        u64 eoff0 = ((u64)(b*64 + cp)*512 + n)*64;
        u64 eoff1 = ((u64)(b*64 + cp + 8)*512 + n)*64;
        if (m == 4 || m == 9){
            __nv_bfloat16* wh = g_bf + (u64)(m == 4 ? 0 : 6)*BUFSZ;
            __nv_bfloat16* wl = wh + BUFSZ;
#pragma unroll
            for (int jj = 0; jj < 8; ++jj){
                int l = jj*8 + lbase;
                float* c = a2[jj];
                u32 h0, l0, h1, l1;
                split2(c[0], c[1], h0, l0);
                split2(c[2], c[3], h1, l1);
                *(u32*)(wh + eoff0 + l) = h0;
                *(u32*)(wl + eoff0 + l) = l0;
                *(u32*)(wh + eoff1 + l) = h1;
                *(u32*)(wl + eoff1 + l) = l1;
            }
        } else {
            float* dst = g_pool + (u64)m*BUFSZ;
#pragma unroll
            for (int jj = 0; jj < 8; ++jj){
                int l = jj*8 + lbase;
                float* c = a2[jj];
                *(float2*)(dst + eoff0 + l) = make_float2(c[0], c[1]);
                *(float2*)(dst + eoff1 + l) = make_float2(c[2], c[3]);
            }
        }
    }
}

// ---------------------------------------------------------------------------
// tensor-core (mma.sync) Horner node step: r' = q + d∘r + A'·r
// A' plain bf16 (2 MMA products: A'h·Bh + A'h·Bl); diagonal exact in epilogue.
// 256 threads, tile 128v x 128l (two bc per CTA), 2-stage cp.async pipeline.
// Stage layout (27648B): [Ah 10240][Bh 8704][Bl 8704]
// Warp (wy = wid&3, wx = wid>>2): rows wy*32..+31, cols wx*64..+63.
// blockIdx.z selects branch: asel+=z, qid+=5z, bslot+=6z, wslot+=6z.
// MODE 0: write r' as bf16 hi/lo.
// MODE 3: z==0 -> fp32 ACC;  z==1 -> out[l+6] = r' + bias (ACC added later).
// ---------------------------------------------------------------------------
#define NODE_SST 27648
#define NODE_SMEM (2*NODE_SST)

__device__ __forceinline__ void node_prefetch(
    u32 sb, const __nv_bfloat16* Ah,
    const __nv_bfloat16* Bh0, const __nv_bfloat16* Bl0,
    int w0, int v0c, int tid){
    // A: 128 rows x 4 segs (hi only)
#pragma unroll
    for (int i = 0; i < 2; ++i){
        int idx = i*256 + tid;              // 0..511
        int row = idx >> 2, seg = idx & 3;
        u64 goff = (u64)(v0c + row)*512 + w0 + seg*8;
        cpa16(sb + row*80 + seg*16, Ah + goff);
    }
    // B: 32 k-rows x 16 segs (segs 0..7 -> bc0, 8..15 -> bc1)
#pragma unroll
    for (int i = 0; i < 2; ++i){
        int idx = i*256 + tid;              // 0..511
        int row = idx >> 4, seg = idx & 15;
        u64 goff = (u64)(seg >> 3)*32768 + (u64)(w0 + row)*64 + (seg & 7)*8;
        cpa16(sb + 10240 + row*272 + seg*16, Bh0 + goff);
        cpa16(sb + 18944 + row*272 + seg*16, Bl0 + goff);
    }
}

template<int MODE>
__global__ __launch_bounds__(256, 2)
void k_node_mma(int asel, int qid, int bslot, int wslot, float* __restrict__ outp){
    extern __shared__ __align__(16) char smn[];
    u32 base = smem_u32(smn);

    int z = blockIdx.z;
    asel += z; qid += 5*z; bslot += 6*z; wslot += 6*z;

    int tid = threadIdx.x, lane = tid & 31, wid = tid >> 5;
    int wy = wid & 3, wx = wid >> 2;
    int bc0 = blockIdx.x*2, v0c = blockIdx.y << 7;

    const __nv_bfloat16* Ah = g_Abf + (u64)(asel*2)*262144;
    const __nv_bfloat16* Bh0 = g_bf + (u64)bslot*BUFSZ + (u64)bc0*32768;
    const __nv_bfloat16* Bl0 = g_bf + (u64)(bslot+1)*BUFSZ + (u64)bc0*32768;
    const float* dvec = g_dA + asel*512;

    float acc[2][8][4];
#pragma unroll
    for (int m = 0; m < 2; ++m)
#pragma unroll
        for (int j = 0; j < 8; ++j)
#pragma unroll
            for (int e = 0; e < 4; ++e) acc[m][j][e] = 0.f;

    // prologue: prefetch chunk 0
    node_prefetch(base, Ah, Bh0, Bl0, 0, v0c, tid);
    cpa_commit();

    for (int kc = 0; kc < 16; ++kc){
        if (kc < 15){
            node_prefetch(base + ((kc+1)&1)*NODE_SST, Ah, Bh0, Bl0,
                          (kc+1)*32, v0c, tid);
            cpa_commit();
            cpa_wait<1>();
        } else {
            cpa_wait<0>();
        }
        __syncthreads();

        u32 sb = base + (kc&1)*NODE_SST;
        u32 uAh = sb, uBh = sb + 10240, uBl = sb + 18944;
#pragma unroll
        for (int ks = 0; ks < 32; ks += 16){
            u32 ah[2][4];
            int arow = lane & 15, acol = ks + (lane >> 4)*8;
#pragma unroll
            for (int m = 0; m < 2; ++m){
                u32 ao = (u32)((wy*32 + m*16 + arow)*40 + acol)*2;
                ldmA(ah[m], uAh + ao);
            }
            int brow = ks + (lane & 15), bcol = (lane >> 4)*8;
#pragma unroll
            for (int g = 0; g < 4; ++g){
                u32 bh[4], bl[4];
                u32 bo = (u32)(brow*136 + (wx*4 + g)*16 + bcol)*2;
                ldmBT(bh, uBh + bo);
                ldmBT(bl, uBl + bo);
#pragma unroll
                for (int m = 0; m < 2; ++m){
#pragma unroll
                    for (int h = 0; h < 2; ++h){
                        float* c = acc[m][g*2 + h];
                        mma16816(c, ah[m], bh[2*h], bh[2*h+1]);
                        mma16816(c, ah[m], bl[2*h], bl[2*h+1]);
                    }
                }
            }
        }
        __syncthreads();   // all reads of stage kc done before it is overwritten
    }

    int lbase = (lane & 3)*2, rbase = lane >> 2;
#pragma unroll
    for (int m = 0; m < 2; ++m){
        int v = v0c + wy*32 + m*16 + rbase;
        float d0 = dvec[v], d1 = dvec[v + 8];
#pragma unroll
        for (int jj = 0; jj < 8; ++jj){
            int nloc = wx*64 + jj*8 + lbase;       // 0..127
            int bcl = bc0 + (nloc >> 6);
            int l = nloc & 63;
            float* c = acc[m][jj];
            const float* qp = g_pool + (u64)qid*BUFSZ + (u64)bcl*32768;
            float2 q0 = *(const float2*)(qp + (u64)v*64 + l);
            float2 q1 = *(const float2*)(qp + (u64)(v+8)*64 + l);
            // reconstruct r (17-bit) for the exact diagonal path
            const __nv_bfloat16* rhp = g_bf + (u64)bslot*BUFSZ + (u64)bcl*32768;
            const __nv_bfloat16* rlp = rhp + BUFSZ;
            float2 r0h = bf2f2(*(const u32*)(rhp + (u64)v*64 + l));
            float2 r0l = bf2f2(*(const u32*)(rlp + (u64)v*64 + l));
            float2 r1h = bf2f2(*(const u32*)(rhp + (u64)(v+8)*64 + l));
            float2 r1l = bf2f2(*(const u32*)(rlp + (u64)(v+8)*64 + l));
            float a0 = c[0] + q0.x + d0*(r0h.x + r0l.x);
            float a1 = c[1] + q0.y + d0*(r0h.y + r0l.y);
            float a2 = c[2] + q1.x + d1*(r1h.x + r1l.x);
            float a3 = c[3] + q1.y + d1*(r1h.y + r1l.y);
            if (MODE == 0){
                __nv_bfloat16* wh = g_bf + (u64)wslot*BUFSZ + (u64)bcl*32768;
                __nv_bfloat16* wl = wh + BUFSZ;
                u32 h0, l0, h1, l1;
                split2(a0, a1, h0, l0);
                split2(a2, a3, h1, l1);
                *(u32*)(wh + (u64)v*64 + l) = h0;
                *(u32*)(wl + (u64)v*64 + l) = l0;
                *(u32*)(wh + (u64)(v+8)*64 + l) = h1;
                *(u32*)(wl + (u64)(v+8)*64 + l) = l1;
            } else {   // MODE 3: z0 -> ACC, z1 -> out (ACC added by k_finaladd)
                if (z == 0){
                    float* op = g_pool + 12ULL*BUFSZ + (u64)bcl*32768;
                    *(float2*)(op + (u64)v*64 + l) = make_float2(a0, a1);
                    *(float2*)(op + (u64)(v+8)*64 + l) = make_float2(a2, a3);
                } else {
                    float bia = g_bias[bcl & 63];
                    float* op = outp + (u64)bcl*32768;
                    a0 += bia; a1 += bia; a2 += bia; a3 += bia;
                    if (l < 58)     op[(u64)v*64 + l + 6]       = a0;
                    if (l + 1 < 58) op[(u64)v*64 + l + 7]       = a1;
                    if (l < 58)     op[(u64)(v+8)*64 + l + 6]   = a2;
                    if (l + 1 < 58) op[(u64)(v+8)*64 + l + 7]   = a3;
                }
            }
        }
    }
}

// out[..., l+6] += ACC[..., l] for l<58; also zero out[..., 0..5]
__global__ void k_finaladd(float* __restrict__ outp){
    u64 i = (u64)blockIdx.x*256 + threadIdx.x;   // 65536*256 = 16.8M
    int l = (int)(i & 63);
    u64 row = i >> 6;
    if (l < 58){
        outp[row*64 + l + 6] += g_pool[12ULL*BUFSZ + i];
    } else {
        outp[row*64 + (l - 58)] = 0.f;           // l-58 in 0..5: zero pad lanes
    }
}

// ---------------------------------------------------------------------------
extern "C" void kernel_launch(void* const* d_in, const int* in_sizes, int n_in,
                              void* d_out, int out_size){
    (void)in_sizes; (void)n_in; (void)out_size;
    const float* x   = (const float*)d_in[0];
    const float* adj = (const float*)d_in[1];
    float* out = (float*)d_out;

    // allow >48KB dynamic smem for the node kernels (idempotent)
    cudaFuncSetAttribute(k_node_mma<0>, cudaFuncAttributeMaxDynamicSharedMemorySize, NODE_SMEM);
    cudaFuncSetAttribute(k_node_mma<3>, cudaFuncAttributeMaxDynamicSharedMemorySize, NODE_SMEM);

    k_deg  <<<512, 256>>>(adj);
    k_norm <<<512, 256>>>(adj);
    k_prepA<<<512, 256>>>();
    k_prep<<<64, 256>>>(
        (const float*)d_in[ 2], (const float*)d_in[ 3], (const float*)d_in[ 4], (const float*)d_in[ 5],
        (const float*)d_in[ 6], (const float*)d_in[ 7], (const float*)d_in[ 8], (const float*)d_in[ 9],
        (const float*)d_in[10], (const float*)d_in[11], (const float*)d_in[12], (const float*)d_in[13],
        (const float*)d_in[14], (const float*)d_in[15], (const float*)d_in[16], (const float*)d_in[17],
        (const float*)d_in[18], (const float*)d_in[19], (const float*)d_in[20], (const float*)d_in[21]);

    k_fused<<<4096, 128>>>(x);

    // Horner: branch0 seed slot 0 (q4), branch1 seed slot 6 (q9);
    // all launches run both branches via gridDim.z = 2.
    dim3 ng3(256, 4, 2);
    k_node_mma<0><<<ng3, 256, NODE_SMEM>>>(0, 3, 0, 2, nullptr);   // step 0
    k_node_mma<0><<<ng3, 256, NODE_SMEM>>>(0, 2, 2, 4, nullptr);   // step 1
    k_node_mma<0><<<ng3, 256, NODE_SMEM>>>(0, 1, 4, 2, nullptr);   // step 2
    k_node_mma<3><<<ng3, 256, NODE_SMEM>>>(0, 0, 2, 0, out);       // finals (both)
    k_finaladd<<<65536, 256>>>(out);
}

// round 14
// speedup vs baseline: 1.2107x; 1.1750x over previous
#include <cuda_runtime.h>
#include <cuda_bf16.h>

typedef unsigned long long u64;
typedef unsigned int u32;

// ---------------------------------------------------------------------------
// Shapes: B=8, C=64, N=512, T=64, valid L=58 (stored padded to 64).
// fp32 pool: q0..q9 (ids 0-9; 4 and 9 unused as fp32), ACC=12.
// bf16 pool slots (BUFSZ each):
//   0/1 seed1(q4) hi/lo, 2/3 & 4/5 branch0 ping-pong,
//   6/7 seed2(q9) hi/lo, 8/9 & 10/11 branch1 ping-pong.
// Node step: r' = q + d∘r + A'·r,  d = diag(M)-1 exact fp32 in epilogue,
// A' = M - diag(M) (entries ~4e-3, bf16). MMA term uses ONE product A'h·rh:
// the A'-term is ~5% of r' magnitude, so its bf16 truncation error is
// attenuated ~20x (validated by the R10 diag-split measurement).
// State r is stored bf16 hi/lo (17-bit) for the exact diagonal path.
// ---------------------------------------------------------------------------
#define BUFSZ (8ULL*64ULL*512ULL*64ULL)

__device__ float g_pool[13ULL*BUFSZ];
__device__ __nv_bfloat16 g_bf[12ULL*BUFSZ];
__device__ __nv_bfloat16 g_Abf[4ULL*512*512];  // slots 0,2 used: [asel*2][v][w] of A'
__device__ float g_dA[2*512];                  // diag(M)-1 per branch

__device__ float g_An [512*512];   // [w][v] = M1[v][w]
__device__ float g_AnT[512*512];   // [w][v] = M2[v][w]
__device__ float g_rd1[512], g_rd2[512];
__device__ __nv_bfloat16 g_W7h[128*448];   // [o][kd] hi
__device__ __nv_bfloat16 g_W7l[128*448];   // [o][kd] lo
__device__ float g_b7[128];
__device__ __nv_bfloat16 g_Wqh[10*64*64];  // [m][out][in] hi  (MMA A-row = out)
__device__ __nv_bfloat16 g_Wql[10*64*64];  // [m][out][in] lo
__device__ float g_bias[64];

// ---------------------------------------------------------------------------
// helpers
// ---------------------------------------------------------------------------
__device__ __forceinline__ u32 smem_u32(const void* p){
    u32 a;
    asm("{ .reg .u64 t; cvta.to.shared.u64 t, %1; cvt.u32.u64 %0, t; }" : "=r"(a) : "l"(p));
    return a;
}
// split a pair of fp32 into packed bf16 hi / bf16 lo
__device__ __forceinline__ void split2(float a0, float a1, u32& hi, u32& lo){
    __nv_bfloat16 h0 = __float2bfloat16(a0);
    __nv_bfloat16 h1 = __float2bfloat16(a1);
    float r0 = a0 - __bfloat162float(h0);
    float r1 = a1 - __bfloat162float(h1);
    union { __nv_bfloat162 v; u32 u; } ch, cl;
    ch.v = __halves2bfloat162(h0, h1);
    cl.v = __halves2bfloat162(__float2bfloat16(r0), __float2bfloat16(r1));
    hi = ch.u; lo = cl.u;
}
__device__ __forceinline__ float2 bf2f2(u32 u){
    union { u32 u; __nv_bfloat162 v; } c; c.u = u;
    return __bfloat1622float2(c.v);
}

// ---------------------------------------------------------------------------
// mma.sync / ldmatrix / cp.async wrappers (baseline PTX, legal on compute_103)
// ---------------------------------------------------------------------------
__device__ __forceinline__ void mma16816(float* c, const u32* a, u32 b0, u32 b1){
    asm volatile(
        "mma.sync.aligned.m16n8k16.row.col.f32.bf16.bf16.f32 "
        "{%0,%1,%2,%3}, {%4,%5,%6,%7}, {%8,%9}, {%0,%1,%2,%3};"
        : "+f"(c[0]), "+f"(c[1]), "+f"(c[2]), "+f"(c[3])
        : "r"(a[0]), "r"(a[1]), "r"(a[2]), "r"(a[3]), "r"(b0), "r"(b1));
}
__device__ __forceinline__ void ldmA(u32* r, u32 addr){
    asm volatile("ldmatrix.sync.aligned.m8n8.x4.shared.b16 {%0,%1,%2,%3}, [%4];"
        : "=r"(r[0]), "=r"(r[1]), "=r"(r[2]), "=r"(r[3]) : "r"(addr));
}
__device__ __forceinline__ void ldmBT(u32* r, u32 addr){
    asm volatile("ldmatrix.sync.aligned.m8n8.x4.trans.shared.b16 {%0,%1,%2,%3}, [%4];"
        : "=r"(r[0]), "=r"(r[1]), "=r"(r[2]), "=r"(r[3]) : "r"(addr));
}
__device__ __forceinline__ void cpa16(u32 dst, const void* src){
    asm volatile("cp.async.cg.shared.global [%0], [%1], 16;" :: "r"(dst), "l"(src));
}
__device__ __forceinline__ void cpa_commit(){
    asm volatile("cp.async.commit_group;" ::: "memory");
}
template<int N>
__device__ __forceinline__ void cpa_wait(){
    asm volatile("cp.async.wait_group %0;" :: "n"(N) : "memory");
}

// ---------------------------------------------------------------------------
// degrees + normalized adjacencies
// ---------------------------------------------------------------------------
__global__ void k_deg(const float* __restrict__ adj){
    int v = blockIdx.x, tid = threadIdx.x;
    float s1 = 0.f, s2 = 0.f;
    for (int w = tid; w < 512; w += 256){
        s1 += adj[v*512 + w];
        s2 += adj[w*512 + v];
    }
    __shared__ float r1[256], r2[256];
    r1[tid] = s1; r2[tid] = s2;
    __syncthreads();
    for (int s = 128; s > 0; s >>= 1){
        if (tid < s){ r1[tid] += r1[tid+s]; r2[tid] += r2[tid+s]; }
        __syncthreads();
    }
    if (tid == 0){
        g_rd1[v] = rsqrtf(r1[0] + 1.f);
        g_rd2[v] = rsqrtf(r2[0] + 1.f);
    }
}

__global__ void k_norm(const float* __restrict__ adj){
    int w = blockIdx.x;
    float dw1 = g_rd1[w], dw2 = g_rd2[w];
    for (int v = threadIdx.x; v < 512; v += 256){
        float e = (v == w) ? 1.f : 0.f;
        g_An [w*512 + v] = g_rd1[v] * (adj[v*512 + w] + e) * dw1;
        g_AnT[w*512 + v] = g_rd2[v] * (adj[w*512 + v] + e) * dw2;
    }
}

// A' = M - diag(M) as plain bf16 [v][w]; d = diag(M) - 1 in fp32.
__global__ void k_prepA(){
    int v = blockIdx.x;
    for (int w = threadIdx.x; w < 512; w += 256){
        float a1 = g_An [w*512 + v];
        float a2 = g_AnT[w*512 + v];
        if (w == v){
            g_dA[v]       = a1 - 1.f;
            g_dA[512 + v] = a2 - 1.f;
            a1 = 0.f; a2 = 0.f;
        }
        g_Abf[0ULL*262144 + v*512 + w] = __float2bfloat16(a1);
        g_Abf[2ULL*262144 + v*512 + w] = __float2bfloat16(a2);
    }
}

// ---------------------------------------------------------------------------
// prep: pad inception weights to k=7 (windows end at l+6), build Horner W'_j,
// split everything to bf16 hi/lo in MMA-friendly layouts.
// ---------------------------------------------------------------------------
__global__ void k_prep(const float* i1w0,const float* i1b0,const float* i1w1,const float* i1b1,
                       const float* i1w2,const float* i1b2,const float* i1w3,const float* i1b3,
                       const float* i2w0,const float* i2b0,const float* i2w1,const float* i2b1,
                       const float* i2w2,const float* i2b2,const float* i2w3,const float* i2b3,
                       const float* m1w,const float* m1b,const float* m2w,const float* m2b){
    int g0 = blockIdx.x*256 + threadIdx.x, gstr = gridDim.x*256;
    const float* WS[8] = {i1w0,i1w1,i1w2,i1w3,i2w0,i2w1,i2w2,i2w3};
    const float* BS[8] = {i1b0,i1b1,i1b2,i1b3,i2b0,i2b1,i2b2,i2b3};
    const int KERN[4] = {2,3,6,7};

    // W7: [o][kd], kd = c*7 + tau
    for (int idx = g0; idx < 128*448; idx += gstr){
        int o = idx / 448, kd = idx - o*448;
        int c = kd / 7, tau = kd - c*7;
        int br = o >> 6, j = (o >> 4) & 3, oc = o & 15;
        int k = KERN[j];
        int t = tau - (7 - k);
        float v = (t >= 0) ? WS[br*4 + j][(oc*64 + c)*k + t] : 0.f;
        __nv_bfloat16 h = __float2bfloat16(v);
        g_W7h[idx] = h;
        g_W7l[idx] = __float2bfloat16(v - __bfloat162float(h));
    }
    for (int idx = g0; idx < 128; idx += gstr){
        int br = idx >> 6, j = (idx >> 4) & 3, oc = idx & 15;
        g_b7[idx] = BS[br*4 + j][oc];
    }
    for (int idx = g0; idx < 64; idx += gstr)
        g_bias[idx] = m1b[idx] + m2b[idx];

    const float COEF[5][5] = {
        {1.f, 1.f,      1.f,      1.f,      1.f     },
        {0.f, 1.f/3.f,  2.f/3.f,  1.f,      1.f     },
        {0.f, 0.f,      1.f/3.f,  1.f/3.f,  0.5f    },
        {0.f, 0.f,      0.f,      1.f/3.f,  1.f/6.f },
        {0.f, 0.f,      0.f,      0.f,      1.f/24.f}};
    // Wq bf16 stored [m][out=c][in=cp] so MMA A-fragment rows are outputs.
    for (int idx = g0; idx < 10*4096; idx += gstr){
        int m = idx >> 12, cp = (idx >> 6) & 63, c = idx & 63;
        int j = m % 5;
        const float* mw = (m < 5) ? m1w : m2w;
        float s = 0.f;
#pragma unroll
        for (int g = 0; g < 5; ++g)
            s += COEF[j][g] * mw[c*320 + g*64 + cp];
        __nv_bfloat16 h = __float2bfloat16(s);
        int widx = (m << 12) + (c << 6) + cp;   // [m][out][in]
        g_Wqh[widx] = h;
        g_Wql[widx] = __float2bfloat16(s - __bfloat162float(h));
    }
}

// ---------------------------------------------------------------------------
// FUSED inception + gate + qgen, all tensor-core (mma.sync split-bf16).
// ---------------------------------------------------------------------------
__global__ __launch_bounds__(128) void k_fused(const float* __restrict__ x){
    __shared__ __align__(16) char sm[38912];
    // stage-1 overlays
    __nv_bfloat16* sAh = (__nv_bfloat16*)(sm);            // [128][40]
    __nv_bfloat16* sAl = (__nv_bfloat16*)(sm + 10240);    // [128][40]
    __nv_bfloat16* sBh = (__nv_bfloat16*)(sm + 20480);    // [32][72]
    __nv_bfloat16* sBl = (__nv_bfloat16*)(sm + 25088);    // [32][72]
    // gate / stage-2 overlays
    float*         sG  = (float*)(sm);                    // [64][72] fp32
    __nv_bfloat16* sWh = (__nv_bfloat16*)(sm);            // [64][72]
    __nv_bfloat16* sWl = (__nv_bfloat16*)(sm + 9216);     // [64][72]
    __nv_bfloat16* sHh = (__nv_bfloat16*)(sm + 20480);    // [64][72]
    __nv_bfloat16* sHl = (__nv_bfloat16*)(sm + 29696);    // [64][72]

    int bn = blockIdx.x;
    int b = bn >> 9, n = bn & 511;
    int tid = threadIdx.x, lane = tid & 31, wid = tid >> 5;
    const float* xb = x + (u64)b*64*32768 + (u64)n*64;   // channel stride 512*64

    u32 uAh = smem_u32(sAh), uAl = smem_u32(sAl);
    u32 uBh = smem_u32(sBh), uBl = smem_u32(sBl);
    u32 uWh = smem_u32(sWh), uWl = smem_u32(sWl);
    u32 uHh = smem_u32(sHh), uHl = smem_u32(sHl);

    float acc[2][8][4];
#pragma unroll
    for (int m = 0; m < 2; ++m)
#pragma unroll
        for (int j = 0; j < 8; ++j)
#pragma unroll
            for (int e = 0; e < 4; ++e) acc[m][j][e] = 0.f;

    // ---------------- stage 1: inception GEMM (K = 448, 14 chunks of 32) ----
    for (int kc = 0; kc < 14; ++kc){
        int w0 = kc*32;
#pragma unroll
        for (int i = 0; i < 4; ++i){
            int idx = i*128 + tid;
            int row = idx >> 2, seg = idx & 3;
            *(uint4*)(sAh + row*40 + seg*8) = *(const uint4*)(g_W7h + row*448 + w0 + seg*8);
            *(uint4*)(sAl + row*40 + seg*8) = *(const uint4*)(g_W7l + row*448 + w0 + seg*8);
        }
        // B: im2col rows kd = w0+row, split fp32 -> bf16 hi/lo
#pragma unroll
        for (int i = 0; i < 8; ++i){
            int idx = i*128 + tid;          // (row, lpair): 32 x 32
            int row = idx >> 5, lp = idx & 31, l = lp*2;
            int kd = w0 + row;
            int c = kd / 7, tau = kd - c*7;
            int t = l + tau;
            float v0 = (t < 64) ? xb[(u64)c*32768 + t] : 0.f;
            float v1 = (t + 1 < 64) ? xb[(u64)c*32768 + t + 1] : 0.f;
            u32 h, lo; split2(v0, v1, h, lo);
            *(u32*)(sBh + row*72 + l) = h;
            *(u32*)(sBl + row*72 + l) = lo;
        }
        __syncthreads();
#pragma unroll
        for (int ks = 0; ks < 32; ks += 16){
            u32 ah[2][4], al[2][4];
            int arow = lane & 15, acol = ks + (lane >> 4)*8;
#pragma unroll
            for (int m = 0; m < 2; ++m){
                u32 ao = (u32)((wid*32 + m*16 + arow)*40 + acol)*2;
                ldmA(ah[m], uAh + ao);
                ldmA(al[m], uAl + ao);
            }
            int brow = ks + (lane & 15), bcol = (lane >> 4)*8;
#pragma unroll
            for (int g = 0; g < 4; ++g){
                u32 bh[4], bl[4];
                u32 bo = (u32)(brow*72 + g*16 + bcol)*2;
                ldmBT(bh, uBh + bo);
                ldmBT(bl, uBl + bo);
#pragma unroll
                for (int m = 0; m < 2; ++m){
#pragma unroll
                    for (int h = 0; h < 2; ++h){
                        float* c = acc[m][g*2 + h];
                        mma16816(c, ah[m], bh[2*h], bh[2*h+1]);
                        mma16816(c, ah[m], bl[2*h], bl[2*h+1]);
                        mma16816(c, al[m], bh[2*h], bh[2*h+1]);
                    }
                }
            }
        }
        __syncthreads();
    }

    // ---------------- gate: h = tanh(filt) * sigmoid(gate) ------------------
    int lbase = (lane & 3)*2, rbase = lane >> 2;
    if (wid >= 2){   // gate rows: o = 64..127 -> write sigmoid to sG
#pragma unroll
        for (int m = 0; m < 2; ++m){
            int o = wid*32 + m*16 + rbase;
#pragma unroll
            for (int jj = 0; jj < 8; ++jj){
                int l = jj*8 + lbase;
                float* c = acc[m][jj];
                float b0 = g_b7[o], b1 = g_b7[o + 8];
                float2 g0, g1;
                g0.x = 1.f/(1.f + expf(-(c[0] + b0)));
                g0.y = 1.f/(1.f + expf(-(c[1] + b0)));
                g1.x = 1.f/(1.f + expf(-(c[2] + b1)));
                g1.y = 1.f/(1.f + expf(-(c[3] + b1)));
                *(float2*)(sG + (o - 64)*72 + l) = g0;
                *(float2*)(sG + (o - 64 + 8)*72 + l) = g1;
            }
        }
    }
    __syncthreads();
    if (wid < 2){    // filt rows: o = c = 0..63 -> h split to sHh/sHl
#pragma unroll
        for (int m = 0; m < 2; ++m){
            int c0 = wid*32 + m*16 + rbase;
#pragma unroll
            for (int jj = 0; jj < 8; ++jj){
                int l = jj*8 + lbase;
                float* c = acc[m][jj];
                float b0 = g_b7[c0], b1 = g_b7[c0 + 8];
                float2 ga = *(const float2*)(sG + c0*72 + l);
                float2 gb = *(const float2*)(sG + (c0 + 8)*72 + l);
                float h0 = tanhf(c[0] + b0) * ga.x;
                float h1 = tanhf(c[1] + b0) * ga.y;
                float h2 = tanhf(c[2] + b1) * gb.x;
                float h3 = tanhf(c[3] + b1) * gb.y;
                u32 ph0, pl0, ph1, pl1;
                split2(h0, h1, ph0, pl0);
                split2(h2, h3, ph1, pl1);
                *(u32*)(sHh + c0*72 + l) = ph0;
                *(u32*)(sHl + c0*72 + l) = pl0;
                *(u32*)(sHh + (c0 + 8)*72 + l) = ph1;
                *(u32*)(sHl + (c0 + 8)*72 + l) = pl1;
            }
        }
    }

    // ---------------- stage 2: q_m = W'_m @ h, m = 0..9 ---------------------
    for (int m = 0; m < 10; ++m){
        __syncthreads();   // sH visible (first iter); sW safe to overwrite
#pragma unroll
        for (int i = 0; i < 4; ++i){
            int idx = i*128 + tid;
            int row = idx >> 3, seg = idx & 7;
            *(uint4*)(sWh + row*72 + seg*8) = *(const uint4*)(g_Wqh + m*4096 + row*64 + seg*8);
            *(uint4*)(sWl + row*72 + seg*8) = *(const uint4*)(g_Wql + m*4096 + row*64 + seg*8);
        }
        __syncthreads();

        float a2[8][4];
#pragma unroll
        for (int j = 0; j < 8; ++j)
#pragma unroll
            for (int e = 0; e < 4; ++e) a2[j][e] = 0.f;

#pragma unroll
        for (int ks = 0; ks < 64; ks += 16){
            u32 ah[4], al[4];
            u32 ao = (u32)((wid*16 + (lane & 15))*72 + ks + (lane >> 4)*8)*2;
            ldmA(ah, uWh + ao);
            ldmA(al, uWl + ao);
            int brow = ks + (lane & 15), bcol = (lane >> 4)*8;
#pragma unroll
            for (int g = 0; g < 4; ++g){
                u32 bh[4], bl[4];
                u32 bo = (u32)(brow*72 + g*16 + bcol)*2;
                ldmBT(bh, uHh + bo);
                ldmBT(bl, uHl + bo);
#pragma unroll
                for (int h = 0; h < 2; ++h){
                    float* c = a2[g*2 + h];
                    mma16816(c, ah, bh[2*h], bh[2*h+1]);
                    mma16816(c, ah, bl[2*h], bl[2*h+1]);
                    mma16816(c, al, bh[2*h], bh[2*h+1]);
                }
            }
        }

        // epilogue for q_m
        int cp = wid*16 + rbase;
        u64 eoff0 = ((u64)(b*64 + cp)*512 + n)*64;
        u64 eoff1 = ((u64)(b*64 + cp + 8)*512 + n)*64;
        if (m == 4 || m == 9){
            __nv_bfloat16* wh = g_bf + (u64)(m == 4 ? 0 : 6)*BUFSZ;
            __nv_bfloat16* wl = wh + BUFSZ;
#pragma unroll
            for (int jj = 0; jj < 8; ++jj){
                int l = jj*8 + lbase;
                float* c = a2[jj];
                u32 h0, l0, h1, l1;
                split2(c[0], c[1], h0, l0);
                split2(c[2], c[3], h1, l1);
                *(u32*)(wh + eoff0 + l) = h0;
                *(u32*)(wl + eoff0 + l) = l0;
                *(u32*)(wh + eoff1 + l) = h1;
                *(u32*)(wl + eoff1 + l) = l1;
            }
        } else {
            float* dst = g_pool + (u64)m*BUFSZ;
#pragma unroll
            for (int jj = 0; jj < 8; ++jj){
                int l = jj*8 + lbase;
                float* c = a2[jj];
                *(float2*)(dst + eoff0 + l) = make_float2(c[0], c[1]);
                *(float2*)(dst + eoff1 + l) = make_float2(c[2], c[3]);
            }
        }
    }
}

// ---------------------------------------------------------------------------
// tensor-core (mma.sync) Horner node step: r' = q + d∘r + A'·r
// SINGLE MMA product (A'h·Bh); exact diagonal in epilogue (reads rh+rl).
// 256 threads, tile 128v x 128l (two bc per CTA), 2-stage cp.async pipeline.
// Stage layout (18944B): [Ah 10240][Bh 8704]
// Warp (wy = wid&3, wx = wid>>2): rows wy*32..+31, cols wx*64..+63.
// blockIdx.z selects branch: asel+=z, qid+=5z, bslot+=6z, wslot+=6z.
// MODE 0: write r' as bf16 hi/lo; MODE 1: fp32 -> ACC; MODE 2: final output.
// ---------------------------------------------------------------------------
#define NODE_SST 18944
#define NODE_SMEM (2*NODE_SST)

__device__ __forceinline__ void node_prefetch(
    u32 sb, const __nv_bfloat16* Ah, const __nv_bfloat16* Bh0,
    int w0, int v0c, int tid){
    // A: 128 rows x 4 segs (hi only)
#pragma unroll
    for (int i = 0; i < 2; ++i){
        int idx = i*256 + tid;              // 0..511
        int row = idx >> 2, seg = idx & 3;
        u64 goff = (u64)(v0c + row)*512 + w0 + seg*8;
        cpa16(sb + row*80 + seg*16, Ah + goff);
    }
    // B: 32 k-rows x 16 segs (segs 0..7 -> bc0, 8..15 -> bc1), hi only
#pragma unroll
    for (int i = 0; i < 2; ++i){
        int idx = i*256 + tid;              // 0..511
        int row = idx >> 4, seg = idx & 15;
        u64 goff = (u64)(seg >> 3)*32768 + (u64)(w0 + row)*64 + (seg & 7)*8;
        cpa16(sb + 10240 + row*272 + seg*16, Bh0 + goff);
    }
}

template<int MODE>
__global__ __launch_bounds__(256, 2)
void k_node_mma(int asel, int qid, int bslot, int wslot, float* __restrict__ outp){
    extern __shared__ __align__(16) char smn[];
    u32 base = smem_u32(smn);

    int z = blockIdx.z;
    asel += z; qid += 5*z; bslot += 6*z; wslot += 6*z;

    int tid = threadIdx.x, lane = tid & 31, wid = tid >> 5;
    int wy = wid & 3, wx = wid >> 2;
    int bc0 = blockIdx.x*2, v0c = blockIdx.y << 7;

    const __nv_bfloat16* Ah = g_Abf + (u64)(asel*2)*262144;
    const __nv_bfloat16* Bh0 = g_bf + (u64)bslot*BUFSZ + (u64)bc0*32768;
    const float* dvec = g_dA + asel*512;

    float acc[2][8][4];
#pragma unroll
    for (int m = 0; m < 2; ++m)
#pragma unroll
        for (int j = 0; j < 8; ++j)
#pragma unroll
            for (int e = 0; e < 4; ++e) acc[m][j][e] = 0.f;

    // prologue: prefetch chunk 0
    node_prefetch(base, Ah, Bh0, 0, v0c, tid);
    cpa_commit();

    for (int kc = 0; kc < 16; ++kc){
        if (kc < 15){
            node_prefetch(base + ((kc+1)&1)*NODE_SST, Ah, Bh0, (kc+1)*32, v0c, tid);
            cpa_commit();
            cpa_wait<1>();
        } else {
            cpa_wait<0>();
        }
        __syncthreads();

        u32 sb = base + (kc&1)*NODE_SST;
        u32 uAh = sb, uBh = sb + 10240;
#pragma unroll
        for (int ks = 0; ks < 32; ks += 16){
            u32 ah[2][4];
            int arow = lane & 15, acol = ks + (lane >> 4)*8;
#pragma unroll
            for (int m = 0; m < 2; ++m){
                u32 ao = (u32)((wy*32 + m*16 + arow)*40 + acol)*2;
                ldmA(ah[m], uAh + ao);
            }
            int brow = ks + (lane & 15), bcol = (lane >> 4)*8;
#pragma unroll
            for (int g = 0; g < 4; ++g){
                u32 bh[4];
                u32 bo = (u32)(brow*136 + (wx*4 + g)*16 + bcol)*2;
                ldmBT(bh, uBh + bo);
#pragma unroll
                for (int m = 0; m < 2; ++m){
#pragma unroll
                    for (int h = 0; h < 2; ++h){
                        float* c = acc[m][g*2 + h];
                        mma16816(c, ah[m], bh[2*h], bh[2*h+1]);
                    }
                }
            }
        }
        __syncthreads();   // all reads of stage kc done before it is overwritten
    }

    int lbase = (lane & 3)*2, rbase = lane >> 2;
#pragma unroll
    for (int m = 0; m < 2; ++m){
        int v = v0c + wy*32 + m*16 + rbase;
        float d0 = dvec[v], d1 = dvec[v + 8];
#pragma unroll
        for (int jj = 0; jj < 8; ++jj){
            int nloc = wx*64 + jj*8 + lbase;       // 0..127
            int bcl = bc0 + (nloc >> 6);
            int l = nloc & 63;
            float* c = acc[m][jj];
            const float* qp = g_pool + (u64)qid*BUFSZ + (u64)bcl*32768;
            float2 q0 = *(const float2*)(qp + (u64)v*64 + l);
            float2 q1 = *(const float2*)(qp + (u64)(v+8)*64 + l);
            // reconstruct r (17-bit) for the exact diagonal path
            const __nv_bfloat16* rhp = g_bf + (u64)bslot*BUFSZ + (u64)bcl*32768;
            const __nv_bfloat16* rlp = rhp + BUFSZ;
            float2 r0h = bf2f2(*(const u32*)(rhp + (u64)v*64 + l));
            float2 r0l = bf2f2(*(const u32*)(rlp + (u64)v*64 + l));
            float2 r1h = bf2f2(*(const u32*)(rhp + (u64)(v+8)*64 + l));
            float2 r1l = bf2f2(*(const u32*)(rlp + (u64)(v+8)*64 + l));
            float a0 = c[0] + q0.x + d0*(r0h.x + r0l.x);
            float a1 = c[1] + q0.y + d0*(r0h.y + r0l.y);
            float a2 = c[2] + q1.x + d1*(r1h.x + r1l.x);
            float a3 = c[3] + q1.y + d1*(r1h.y + r1l.y);
            if (MODE == 0){
                __nv_bfloat16* wh = g_bf + (u64)wslot*BUFSZ + (u64)bcl*32768;
                __nv_bfloat16* wl = wh + BUFSZ;
                u32 h0, l0, h1, l1;
                split2(a0, a1, h0, l0);
                split2(a2, a3, h1, l1);
                *(u32*)(wh + (u64)v*64 + l) = h0;
                *(u32*)(wl + (u64)v*64 + l) = l0;
                *(u32*)(wh + (u64)(v+8)*64 + l) = h1;
                *(u32*)(wl + (u64)(v+8)*64 + l) = l1;
            } else if (MODE == 1){
                float* op = g_pool + 12ULL*BUFSZ + (u64)bcl*32768;
                *(float2*)(op + (u64)v*64 + l) = make_float2(a0, a1);
                *(float2*)(op + (u64)(v+8)*64 + l) = make_float2(a2, a3);
            } else {
                const float* ap = g_pool + 12ULL*BUFSZ + (u64)bcl*32768;
                float bia = g_bias[bcl & 63];
                float* op = outp + (u64)bcl*32768;
                a0 += ap[(u64)v*64 + l] + bia;
                a1 += ap[(u64)v*64 + l + 1] + bia;
                a2 += ap[(u64)(v+8)*64 + l] + bia;
                a3 += ap[(u64)(v+8)*64 + l + 1] + bia;
                if (l < 58)     op[(u64)v*64 + l + 6]       = a0;
                if (l + 1 < 58) op[(u64)v*64 + l + 7]       = a1;
                if (l < 58)     op[(u64)(v+8)*64 + l + 6]   = a2;
                if (l + 1 < 58) op[(u64)(v+8)*64 + l + 7]   = a3;
            }
        }
    }
}

__global__ void k_zeropad(float* __restrict__ outp){
    int i = blockIdx.x*256 + threadIdx.x;
    if (i < 8*64*512*6){
        int row = i / 6, t = i - row*6;
        outp[(u64)row*64 + t] = 0.f;
    }
}

// ---------------------------------------------------------------------------
extern "C" void kernel_launch(void* const* d_in, const int* in_sizes, int n_in,
                              void* d_out, int out_size){
    (void)in_sizes; (void)n_in; (void)out_size;
    const float* x   = (const float*)d_in[0];
    const float* adj = (const float*)d_in[1];
    float* out = (float*)d_out;

    // allow >48KB dynamic smem for the node kernels (idempotent)
    cudaFuncSetAttribute(k_node_mma<0>, cudaFuncAttributeMaxDynamicSharedMemorySize, NODE_SMEM);
    cudaFuncSetAttribute(k_node_mma<1>, cudaFuncAttributeMaxDynamicSharedMemorySize, NODE_SMEM);
    cudaFuncSetAttribute(k_node_mma<2>, cudaFuncAttributeMaxDynamicSharedMemorySize, NODE_SMEM);

    k_deg  <<<512, 256>>>(adj);
    k_norm <<<512, 256>>>(adj);
    k_prepA<<<512, 256>>>();
    k_prep<<<64, 256>>>(
        (const float*)d_in[ 2], (const float*)d_in[ 3], (const float*)d_in[ 4], (const float*)d_in[ 5],
        (const float*)d_in[ 6], (const float*)d_in[ 7], (const float*)d_in[ 8], (const float*)d_in[ 9],
        (const float*)d_in[10], (const float*)d_in[11], (const float*)d_in[12], (const float*)d_in[13],
        (const float*)d_in[14], (const float*)d_in[15], (const float*)d_in[16], (const float*)d_in[17],
        (const float*)d_in[18], (const float*)d_in[19], (const float*)d_in[20], (const float*)d_in[21]);

    k_fused<<<4096, 128>>>(x);

    // Horner: branch0 seed slot 0 (q4), branch1 seed slot 6 (q9);
    // merged launches run both branches via gridDim.z = 2.  (R10 structure)
    dim3 ng3(256, 4, 2);
    k_node_mma<0><<<ng3, 256, NODE_SMEM>>>(0, 3, 0, 2, nullptr);   // step 0
    k_node_mma<0><<<ng3, 256, NODE_SMEM>>>(0, 2, 2, 4, nullptr);   // step 1
    k_node_mma<0><<<ng3, 256, NODE_SMEM>>>(0, 1, 4, 2, nullptr);   // step 2
    dim3 ng(256, 4, 1);
    k_node_mma<1><<<ng, 256, NODE_SMEM>>>(0, 0, 2, 0, nullptr);    // b0 final -> ACC
    k_node_mma<2><<<ng, 256, NODE_SMEM>>>(1, 5, 8, 0, out);        // b1 final -> out

    k_zeropad<<<6144, 256>>>(out);
}

// round 15
// speedup vs baseline: 1.2540x; 1.0357x over previous
#include <cuda_runtime.h>
#include <cuda_bf16.h>

typedef unsigned long long u64;
typedef unsigned int u32;

// ---------------------------------------------------------------------------
// Shapes: B=8, C=64, N=512, T=64, valid L=58 (stored padded to 64).
// fp32 pool: q0..q9 (ids 0-9; 4 and 9 unused as fp32), ACC=12.
// bf16 pool slots (BUFSZ each):
//   0/1 seed1(q4) hi/lo, 2/3 & 4/5 branch0 ping-pong,
//   6/7 seed2(q9) hi/lo, 8/9 & 10/11 branch1 ping-pong.
// Node step: r' = q + d∘r + A'·r,  d = diag(M)-1 exact fp32 in epilogue,
// A' = M - diag(M) (entries ~4e-3, bf16), ONE MMA product A'h·rh.
// State r stored bf16 hi/lo (17-bit) for the exact diagonal path.
// ---------------------------------------------------------------------------
#define BUFSZ (8ULL*64ULL*512ULL*64ULL)

__device__ float g_pool[13ULL*BUFSZ];
__device__ __nv_bfloat16 g_bf[12ULL*BUFSZ];
__device__ __nv_bfloat16 g_Abf[4ULL*512*512];  // slots 0,2 used: [asel*2][v][w] of A'
__device__ float g_dA[2*512];                  // diag(M)-1 per branch

__device__ float g_An [512*512];   // [w][v] = M1[v][w]
__device__ float g_AnT[512*512];   // [w][v] = M2[v][w]
__device__ float g_rd1[512], g_rd2[512];
__device__ __nv_bfloat16 g_W7h[128*448];   // [o][kd] hi
__device__ __nv_bfloat16 g_W7l[128*448];   // [o][kd] lo
__device__ float g_b7[128];
__device__ __nv_bfloat16 g_Wqh[10*64*64];  // [m][out][in] hi  (MMA A-row = out)
__device__ __nv_bfloat16 g_Wql[10*64*64];  // [m][out][in] lo
__device__ float g_bias[64];

// ---------------------------------------------------------------------------
// helpers
// ---------------------------------------------------------------------------
__device__ __forceinline__ u32 smem_u32(const void* p){
    u32 a;
    asm("{ .reg .u64 t; cvta.to.shared.u64 t, %1; cvt.u32.u64 %0, t; }" : "=r"(a) : "l"(p));
    return a;
}
// split a pair of fp32 into packed bf16 hi / bf16 lo
__device__ __forceinline__ void split2(float a0, float a1, u32& hi, u32& lo){
    __nv_bfloat16 h0 = __float2bfloat16(a0);
    __nv_bfloat16 h1 = __float2bfloat16(a1);
    float r0 = a0 - __bfloat162float(h0);
    float r1 = a1 - __bfloat162float(h1);
    union { __nv_bfloat162 v; u32 u; } ch, cl;
    ch.v = __halves2bfloat162(h0, h1);
    cl.v = __halves2bfloat162(__float2bfloat16(r0), __float2bfloat16(r1));
    hi = ch.u; lo = cl.u;
}
__device__ __forceinline__ float2 bf2f2(u32 u){
    union { u32 u; __nv_bfloat162 v; } c; c.u = u;
    return __bfloat1622float2(c.v);
}

// ---------------------------------------------------------------------------
// mma.sync / ldmatrix / cp.async wrappers (baseline PTX, legal on compute_103)
// ---------------------------------------------------------------------------
__device__ __forceinline__ void mma16816(float* c, const u32* a, u32 b0, u32 b1){
    asm volatile(
        "mma.sync.aligned.m16n8k16.row.col.f32.bf16.bf16.f32 "
        "{%0,%1,%2,%3}, {%4,%5,%6,%7}, {%8,%9}, {%0,%1,%2,%3};"
        : "+f"(c[0]), "+f"(c[1]), "+f"(c[2]), "+f"(c[3])
        : "r"(a[0]), "r"(a[1]), "r"(a[2]), "r"(a[3]), "r"(b0), "r"(b1));
}
__device__ __forceinline__ void ldmA(u32* r, u32 addr){
    asm volatile("ldmatrix.sync.aligned.m8n8.x4.shared.b16 {%0,%1,%2,%3}, [%4];"
        : "=r"(r[0]), "=r"(r[1]), "=r"(r[2]), "=r"(r[3]) : "r"(addr));
}
__device__ __forceinline__ void ldmBT(u32* r, u32 addr){
    asm volatile("ldmatrix.sync.aligned.m8n8.x4.trans.shared.b16 {%0,%1,%2,%3}, [%4];"
        : "=r"(r[0]), "=r"(r[1]), "=r"(r[2]), "=r"(r[3]) : "r"(addr));
}
__device__ __forceinline__ void cpa16(u32 dst, const void* src){
    asm volatile("cp.async.cg.shared.global [%0], [%1], 16;" :: "r"(dst), "l"(src));
}
__device__ __forceinline__ void cpa_commit(){
    asm volatile("cp.async.commit_group;" ::: "memory");
}
template<int N>
__device__ __forceinline__ void cpa_wait(){
    asm volatile("cp.async.wait_group %0;" :: "n"(N) : "memory");
}

// ---------------------------------------------------------------------------
// degrees + normalized adjacencies
// ---------------------------------------------------------------------------
__global__ void k_deg(const float* __restrict__ adj){
    int v = blockIdx.x, tid = threadIdx.x;
    float s1 = 0.f, s2 = 0.f;
    for (int w = tid; w < 512; w += 256){
        s1 += adj[v*512 + w];
        s2 += adj[w*512 + v];
    }
    __shared__ float r1[256], r2[256];
    r1[tid] = s1; r2[tid] = s2;
    __syncthreads();
    for (int s = 128; s > 0; s >>= 1){
        if (tid < s){ r1[tid] += r1[tid+s]; r2[tid] += r2[tid+s]; }
        __syncthreads();
    }
    if (tid == 0){
        g_rd1[v] = rsqrtf(r1[0] + 1.f);
        g_rd2[v] = rsqrtf(r2[0] + 1.f);
    }
}

__global__ void k_norm(const float* __restrict__ adj){
    int w = blockIdx.x;
    float dw1 = g_rd1[w], dw2 = g_rd2[w];
    for (int v = threadIdx.x; v < 512; v += 256){
        float e = (v == w) ? 1.f : 0.f;
        g_An [w*512 + v] = g_rd1[v] * (adj[v*512 + w] + e) * dw1;
        g_AnT[w*512 + v] = g_rd2[v] * (adj[w*512 + v] + e) * dw2;
    }
}

// A' = M - diag(M) as plain bf16 [v][w]; d = diag(M) - 1 in fp32.
__global__ void k_prepA(){
    int v = blockIdx.x;
    for (int w = threadIdx.x; w < 512; w += 256){
        float a1 = g_An [w*512 + v];
        float a2 = g_AnT[w*512 + v];
        if (w == v){
            g_dA[v]       = a1 - 1.f;
            g_dA[512 + v] = a2 - 1.f;
            a1 = 0.f; a2 = 0.f;
        }
        g_Abf[0ULL*262144 + v*512 + w] = __float2bfloat16(a1);
        g_Abf[2ULL*262144 + v*512 + w] = __float2bfloat16(a2);
    }
}

// ---------------------------------------------------------------------------
// prep: pad inception weights to k=7 (windows end at l+6), build Horner W'_j,
// split everything to bf16 hi/lo in MMA-friendly layouts.
// ---------------------------------------------------------------------------
__global__ void k_prep(const float* i1w0,const float* i1b0,const float* i1w1,const float* i1b1,
                       const float* i1w2,const float* i1b2,const float* i1w3,const float* i1b3,
                       const float* i2w0,const float* i2b0,const float* i2w1,const float* i2b1,
                       const float* i2w2,const float* i2b2,const float* i2w3,const float* i2b3,
                       const float* m1w,const float* m1b,const float* m2w,const float* m2b){
    int g0 = blockIdx.x*256 + threadIdx.x, gstr = gridDim.x*256;
    const float* WS[8] = {i1w0,i1w1,i1w2,i1w3,i2w0,i2w1,i2w2,i2w3};
    const float* BS[8] = {i1b0,i1b1,i1b2,i1b3,i2b0,i2b1,i2b2,i2b3};
    const int KERN[4] = {2,3,6,7};

    // W7: [o][kd], kd = c*7 + tau
    for (int idx = g0; idx < 128*448; idx += gstr){
        int o = idx / 448, kd = idx - o*448;
        int c = kd / 7, tau = kd - c*7;
        int br = o >> 6, j = (o >> 4) & 3, oc = o & 15;
        int k = KERN[j];
        int t = tau - (7 - k);
        float v = (t >= 0) ? WS[br*4 + j][(oc*64 + c)*k + t] : 0.f;
        __nv_bfloat16 h = __float2bfloat16(v);
        g_W7h[idx] = h;
        g_W7l[idx] = __float2bfloat16(v - __bfloat162float(h));
    }
    for (int idx = g0; idx < 128; idx += gstr){
        int br = idx >> 6, j = (idx >> 4) & 3, oc = idx & 15;
        g_b7[idx] = BS[br*4 + j][oc];
    }
    for (int idx = g0; idx < 64; idx += gstr)
        g_bias[idx] = m1b[idx] + m2b[idx];

    const float COEF[5][5] = {
        {1.f, 1.f,      1.f,      1.f,      1.f     },
        {0.f, 1.f/3.f,  2.f/3.f,  1.f,      1.f     },
        {0.f, 0.f,      1.f/3.f,  1.f/3.f,  0.5f    },
        {0.f, 0.f,      0.f,      1.f/3.f,  1.f/6.f },
        {0.f, 0.f,      0.f,      0.f,      1.f/24.f}};
    // Wq bf16 stored [m][out=c][in=cp] so MMA A-fragment rows are outputs.
    for (int idx = g0; idx < 10*4096; idx += gstr){
        int m = idx >> 12, cp = (idx >> 6) & 63, c = idx & 63;
        int j = m % 5;
        const float* mw = (m < 5) ? m1w : m2w;
        float s = 0.f;
#pragma unroll
        for (int g = 0; g < 5; ++g)
            s += COEF[j][g] * mw[c*320 + g*64 + cp];
        __nv_bfloat16 h = __float2bfloat16(s);
        int widx = (m << 12) + (c << 6) + cp;   // [m][out][in]
        g_Wqh[widx] = h;
        g_Wql[widx] = __float2bfloat16(s - __bfloat162float(h));
    }
}

// ---------------------------------------------------------------------------
// FUSED inception + gate + qgen, all tensor-core (mma.sync split-bf16).
// ---------------------------------------------------------------------------
__global__ __launch_bounds__(128) void k_fused(const float* __restrict__ x){
    __shared__ __align__(16) char sm[38912];
    // stage-1 overlays
    __nv_bfloat16* sAh = (__nv_bfloat16*)(sm);            // [128][40]
    __nv_bfloat16* sAl = (__nv_bfloat16*)(sm + 10240);    // [128][40]
    __nv_bfloat16* sBh = (__nv_bfloat16*)(sm + 20480);    // [32][72]
    __nv_bfloat16* sBl = (__nv_bfloat16*)(sm + 25088);    // [32][72]
    // gate / stage-2 overlays
    float*         sG  = (float*)(sm);                    // [64][72] fp32
    __nv_bfloat16* sWh = (__nv_bfloat16*)(sm);            // [64][72]
    __nv_bfloat16* sWl = (__nv_bfloat16*)(sm + 9216);     // [64][72]
    __nv_bfloat16* sHh = (__nv_bfloat16*)(sm + 20480);    // [64][72]
    __nv_bfloat16* sHl = (__nv_bfloat16*)(sm + 29696);    // [64][72]

    int bn = blockIdx.x;
    int b = bn >> 9, n = bn & 511;
    int tid = threadIdx.x, lane = tid & 31, wid = tid >> 5;
    const float* xb = x + (u64)b*64*32768 + (u64)n*64;   // channel stride 512*64

    u32 uAh = smem_u32(sAh), uAl = smem_u32(sAl);
    u32 uBh = smem_u32(sBh), uBl = smem_u32(sBl);
    u32 uWh = smem_u32(sWh), uWl = smem_u32(sWl);
    u32 uHh = smem_u32(sHh), uHl = smem_u32(sHl);

    float acc[2][8][4];
#pragma unroll
    for (int m = 0; m < 2; ++m)
#pragma unroll
        for (int j = 0; j < 8; ++j)
#pragma unroll
            for (int e = 0; e < 4; ++e) acc[m][j][e] = 0.f;

    // ---------------- stage 1: inception GEMM (K = 448, 14 chunks of 32) ----
    for (int kc = 0; kc < 14; ++kc){
        int w0 = kc*32;
#pragma unroll
        for (int i = 0; i < 4; ++i){
            int idx = i*128 + tid;
            int row = idx >> 2, seg = idx & 3;
            *(uint4*)(sAh + row*40 + seg*8) = *(const uint4*)(g_W7h + row*448 + w0 + seg*8);
            *(uint4*)(sAl + row*40 + seg*8) = *(const uint4*)(g_W7l + row*448 + w0 + seg*8);
        }
        // B: im2col rows kd = w0+row, split fp32 -> bf16 hi/lo
#pragma unroll
        for (int i = 0; i < 8; ++i){
            int idx = i*128 + tid;          // (row, lpair): 32 x 32
            int row = idx >> 5, lp = idx & 31, l = lp*2;
            int kd = w0 + row;
            int c = kd / 7, tau = kd - c*7;
            int t = l + tau;
            float v0 = (t < 64) ? xb[(u64)c*32768 + t] : 0.f;
            float v1 = (t + 1 < 64) ? xb[(u64)c*32768 + t + 1] : 0.f;
            u32 h, lo; split2(v0, v1, h, lo);
            *(u32*)(sBh + row*72 + l) = h;
            *(u32*)(sBl + row*72 + l) = lo;
        }
        __syncthreads();
#pragma unroll
        for (int ks = 0; ks < 32; ks += 16){
            u32 ah[2][4], al[2][4];
            int arow = lane & 15, acol = ks + (lane >> 4)*8;
#pragma unroll
            for (int m = 0; m < 2; ++m){
                u32 ao = (u32)((wid*32 + m*16 + arow)*40 + acol)*2;
                ldmA(ah[m], uAh + ao);
                ldmA(al[m], uAl + ao);
            }
            int brow = ks + (lane & 15), bcol = (lane >> 4)*8;
#pragma unroll
            for (int g = 0; g < 4; ++g){
                u32 bh[4], bl[4];
                u32 bo = (u32)(brow*72 + g*16 + bcol)*2;
                ldmBT(bh, uBh + bo);
                ldmBT(bl, uBl + bo);
#pragma unroll
                for (int m = 0; m < 2; ++m){
#pragma unroll
                    for (int h = 0; h < 2; ++h){
                        float* c = acc[m][g*2 + h];
                        mma16816(c, ah[m], bh[2*h], bh[2*h+1]);
                        mma16816(c, ah[m], bl[2*h], bl[2*h+1]);
                        mma16816(c, al[m], bh[2*h], bh[2*h+1]);
                    }
                }
            }
        }
        __syncthreads();
    }

    // ---------------- gate: h = tanh(filt) * sigmoid(gate) ------------------
    int lbase = (lane & 3)*2, rbase = lane >> 2;
    if (wid >= 2){   // gate rows: o = 64..127 -> write sigmoid to sG
#pragma unroll
        for (int m = 0; m < 2; ++m){
            int o = wid*32 + m*16 + rbase;
#pragma unroll
            for (int jj = 0; jj < 8; ++jj){
                int l = jj*8 + lbase;
                float* c = acc[m][jj];
                float b0 = g_b7[o], b1 = g_b7[o + 8];
                float2 g0, g1;
                g0.x = 1.f/(1.f + expf(-(c[0] + b0)));
                g0.y = 1.f/(1.f + expf(-(c[1] + b0)));
                g1.x = 1.f/(1.f + expf(-(c[2] + b1)));
                g1.y = 1.f/(1.f + expf(-(c[3] + b1)));
                *(float2*)(sG + (o - 64)*72 + l) = g0;
                *(float2*)(sG + (o - 64 + 8)*72 + l) = g1;
            }
        }
    }
    __syncthreads();
    if (wid < 2){    // filt rows: o = c = 0..63 -> h split to sHh/sHl
#pragma unroll
        for (int m = 0; m < 2; ++m){
            int c0 = wid*32 + m*16 + rbase;
#pragma unroll
            for (int jj = 0; jj < 8; ++jj){
                int l = jj*8 + lbase;
                float* c = acc[m][jj];
                float b0 = g_b7[c0], b1 = g_b7[c0 + 8];
                float2 ga = *(const float2*)(sG + c0*72 + l);
                float2 gb = *(const float2*)(sG + (c0 + 8)*72 + l);
                float h0 = tanhf(c[0] + b0) * ga.x;
                float h1 = tanhf(c[1] + b0) * ga.y;
                float h2 = tanhf(c[2] + b1) * gb.x;
                float h3 = tanhf(c[3] + b1) * gb.y;
                u32 ph0, pl0, ph1, pl1;
                split2(h0, h1, ph0, pl0);
                split2(h2, h3, ph1, pl1);
                *(u32*)(sHh + c0*72 + l) = ph0;
                *(u32*)(sHl + c0*72 + l) = pl0;
                *(u32*)(sHh + (c0 + 8)*72 + l) = ph1;
                *(u32*)(sHl + (c0 + 8)*72 + l) = pl1;
            }
        }
    }

    // ---------------- stage 2: q_m = W'_m @ h, m = 0..9 ---------------------
    for (int m = 0; m < 10; ++m){
        __syncthreads();   // sH visible (first iter); sW safe to overwrite
#pragma unroll
        for (int i = 0; i < 4; ++i){
            int idx = i*128 + tid;
            int row = idx >> 3, seg = idx & 7;
            *(uint4*)(sWh + row*72 + seg*8) = *(const uint4*)(g_Wqh + m*4096 + row*64 + seg*8);
            *(uint4*)(sWl + row*72 + seg*8) = *(const uint4*)(g_Wql + m*4096 + row*64 + seg*8);
        }
        __syncthreads();

        float a2[8][4];
#pragma unroll
        for (int j = 0; j < 8; ++j)
#pragma unroll
            for (int e = 0; e < 4; ++e) a2[j][e] = 0.f;

#pragma unroll
        for (int ks = 0; ks < 64; ks += 16){
            u32 ah[4], al[4];
            u32 ao = (u32)((wid*16 + (lane & 15))*72 + ks + (lane >> 4)*8)*2;
            ldmA(ah, uWh + ao);
            ldmA(al, uWl + ao);
            int brow = ks + (lane & 15), bcol = (lane >> 4)*8;
#pragma unroll
            for (int g = 0; g < 4; ++g){
                u32 bh[4], bl[4];
                u32 bo = (u32)(brow*72 + g*16 + bcol)*2;
                ldmBT(bh, uHh + bo);
                ldmBT(bl, uHl + bo);
#pragma unroll
                for (int h = 0; h < 2; ++h){
                    float* c = a2[g*2 + h];
                    mma16816(c, ah, bh[2*h], bh[2*h+1]);
                    mma16816(c, ah, bl[2*h], bl[2*h+1]);
                    mma16816(c, al, bh[2*h], bh[2*h+1]);
                }
            }
        }

        // epilogue for q_m
        int cp = wid*16 + rbase;
        u64 eoff0 = ((u64)(b*64 + cp)*512 + n)*64;
        u64 eoff1 = ((u64)(b*64 + cp + 8)*512 + n)*64;
        if (m == 4 || m == 9){
            __nv_bfloat16* wh = g_bf + (u64)(m == 4 ? 0 : 6)*BUFSZ;
            __nv_bfloat16* wl = wh + BUFSZ;
#pragma unroll
            for (int jj = 0; jj < 8; ++jj){
                int l = jj*8 + lbase;
                float* c = a2[jj];
                u32 h0, l0, h1, l1;
                split2(c[0], c[1], h0, l0);
                split2(c[2], c[3], h1, l1);
                *(u32*)(wh + eoff0 + l) = h0;
                *(u32*)(wl + eoff0 + l) = l0;
                *(u32*)(wh + eoff1 + l) = h1;
                *(u32*)(wl + eoff1 + l) = l1;
            }
        } else {
            float* dst = g_pool + (u64)m*BUFSZ;
#pragma unroll
            for (int jj = 0; jj < 8; ++jj){
                int l = jj*8 + lbase;
                float* c = a2[jj];
                *(float2*)(dst + eoff0 + l) = make_float2(c[0], c[1]);
                *(float2*)(dst + eoff1 + l) = make_float2(c[2], c[3]);
            }
        }
    }
}

// ---------------------------------------------------------------------------
// tensor-core (mma.sync) Horner node step: r' = q + d∘r + A'·r
// SINGLE MMA product (A'h·Bh); exact diagonal in epilogue (reads rh+rl).
// 256 threads, tile 128v x 128l (two bc per CTA).
// 3-stage cp.async pipeline, ONE __syncthreads per chunk (CUTLASS multistage:
// prefetch at iter kc overwrites chunk kc-1's stage, safe past top barrier).
// Stage layout (18944B): [Ah 10240][Bh 8704]
// blockIdx.z selects branch: asel+=z, qid+=5z, bslot+=6z, wslot+=6z.
// MODE 0: write r' as bf16 hi/lo; MODE 1: fp32 -> ACC; MODE 2: final output.
// ---------------------------------------------------------------------------
#define NODE_SST 18944
#define NODE_NSTAGE 3
#define NODE_SMEM (NODE_NSTAGE*NODE_SST)

__device__ __forceinline__ void node_prefetch(
    u32 sb, const __nv_bfloat16* Ah, const __nv_bfloat16* Bh0,
    int w0, int v0c, int tid){
    // A: 128 rows x 4 segs (hi only)
#pragma unroll
    for (int i = 0; i < 2; ++i){
        int idx = i*256 + tid;              // 0..511
        int row = idx >> 2, seg = idx & 3;
        u64 goff = (u64)(v0c + row)*512 + w0 + seg*8;
        cpa16(sb + row*80 + seg*16, Ah + goff);
    }
    // B: 32 k-rows x 16 segs (segs 0..7 -> bc0, 8..15 -> bc1), hi only
#pragma unroll
    for (int i = 0; i < 2; ++i){
        int idx = i*256 + tid;              // 0..511
        int row = idx >> 4, seg = idx & 15;
        u64 goff = (u64)(seg >> 3)*32768 + (u64)(w0 + row)*64 + (seg & 7)*8;
        cpa16(sb + 10240 + row*272 + seg*16, Bh0 + goff);
    }
}

template<int MODE>
__global__ __launch_bounds__(256, 2)
void k_node_mma(int asel, int qid, int bslot, int wslot, float* __restrict__ outp){
    extern __shared__ __align__(16) char smn[];
    u32 base = smem_u32(smn);

    int z = blockIdx.z;
    asel += z; qid += 5*z; bslot += 6*z; wslot += 6*z;

    int tid = threadIdx.x, lane = tid & 31, wid = tid >> 5;
    int wy = wid & 3, wx = wid >> 2;
    int bc0 = blockIdx.x*2, v0c = blockIdx.y << 7;

    const __nv_bfloat16* Ah = g_Abf + (u64)(asel*2)*262144;
    const __nv_bfloat16* Bh0 = g_bf + (u64)bslot*BUFSZ + (u64)bc0*32768;
    const float* dvec = g_dA + asel*512;

    float acc[2][8][4];
#pragma unroll
    for (int m = 0; m < 2; ++m)
#pragma unroll
        for (int j = 0; j < 8; ++j)
#pragma unroll
            for (int e = 0; e < 4; ++e) acc[m][j][e] = 0.f;

    // prologue: prefetch chunks 0 and 1 (stages 0, 1)
    node_prefetch(base, Ah, Bh0, 0, v0c, tid);
    cpa_commit();
    node_prefetch(base + NODE_SST, Ah, Bh0, 32, v0c, tid);
    cpa_commit();

    int st = 0;       // stage of current chunk kc
    int pst = 2;      // stage to prefetch into (chunk kc+2)
    for (int kc = 0; kc < 16; ++kc){
        cpa_wait<1>();       // group kc complete (only kc+1 may be pending)
        __syncthreads();     // chunk kc visible; all warps done MMA(kc-1)
        if (kc + 2 < 16)
            node_prefetch(base + pst*NODE_SST, Ah, Bh0, (kc+2)*32, v0c, tid);
        cpa_commit();        // commit (possibly empty) group kc+2

        u32 sb = base + st*NODE_SST;
        u32 uAh = sb, uBh = sb + 10240;
#pragma unroll
        for (int ks = 0; ks < 32; ks += 16){
            u32 ah[2][4];
            int arow = lane & 15, acol = ks + (lane >> 4)*8;
#pragma unroll
            for (int m = 0; m < 2; ++m){
                u32 ao = (u32)((wy*32 + m*16 + arow)*40 + acol)*2;
                ldmA(ah[m], uAh + ao);
            }
            int brow = ks + (lane & 15), bcol = (lane >> 4)*8;
#pragma unroll
            for (int g = 0; g < 4; ++g){
                u32 bh[4];
                u32 bo = (u32)(brow*136 + (wx*4 + g)*16 + bcol)*2;
                ldmBT(bh, uBh + bo);
#pragma unroll
                for (int m = 0; m < 2; ++m){
#pragma unroll
                    for (int h = 0; h < 2; ++h){
                        float* c = acc[m][g*2 + h];
                        mma16816(c, ah[m], bh[2*h], bh[2*h+1]);
                    }
                }
            }
        }
        st = (st == 2) ? 0 : st + 1;
        pst = (pst == 2) ? 0 : pst + 1;
    }

    int lbase = (lane & 3)*2, rbase = lane >> 2;
#pragma unroll
    for (int m = 0; m < 2; ++m){
        int v = v0c + wy*32 + m*16 + rbase;
        float d0 = dvec[v], d1 = dvec[v + 8];
#pragma unroll
        for (int jj = 0; jj < 8; ++jj){
            int nloc = wx*64 + jj*8 + lbase;       // 0..127
            int bcl = bc0 + (nloc >> 6);
            int l = nloc & 63;
            float* c = acc[m][jj];
            const float* qp = g_pool + (u64)qid*BUFSZ + (u64)bcl*32768;
            float2 q0 = *(const float2*)(qp + (u64)v*64 + l);
            float2 q1 = *(const float2*)(qp + (u64)(v+8)*64 + l);
            // reconstruct r (17-bit) for the exact diagonal path
            const __nv_bfloat16* rhp = g_bf + (u64)bslot*BUFSZ + (u64)bcl*32768;
            const __nv_bfloat16* rlp = rhp + BUFSZ;
            float2 r0h = bf2f2(*(const u32*)(rhp + (u64)v*64 + l));
            float2 r0l = bf2f2(*(const u32*)(rlp + (u64)v*64 + l));
            float2 r1h = bf2f2(*(const u32*)(rhp + (u64)(v+8)*64 + l));
            float2 r1l = bf2f2(*(const u32*)(rlp + (u64)(v+8)*64 + l));
            float a0 = c[0] + q0.x + d0*(r0h.x + r0l.x);
            float a1 = c[1] + q0.y + d0*(r0h.y + r0l.y);
            float a2 = c[2] + q1.x + d1*(r1h.x + r1l.x);
            float a3 = c[3] + q1.y + d1*(r1h.y + r1l.y);
            if (MODE == 0){
                __nv_bfloat16* wh = g_bf + (u64)wslot*BUFSZ + (u64)bcl*32768;
                __nv_bfloat16* wl = wh + BUFSZ;
                u32 h0, l0, h1, l1;
                split2(a0, a1, h0, l0);
                split2(a2, a3, h1, l1);
                *(u32*)(wh + (u64)v*64 + l) = h0;
                *(u32*)(wl + (u64)v*64 + l) = l0;
                *(u32*)(wh + (u64)(v+8)*64 + l) = h1;
                *(u32*)(wl + (u64)(v+8)*64 + l) = l1;
            } else if (MODE == 1){
                float* op = g_pool + 12ULL*BUFSZ + (u64)bcl*32768;
                *(float2*)(op + (u64)v*64 + l) = make_float2(a0, a1);
                *(float2*)(op + (u64)(v+8)*64 + l) = make_float2(a2, a3);
            } else {
                const float* ap = g_pool + 12ULL*BUFSZ + (u64)bcl*32768;
                float bia = g_bias[bcl & 63];
                float* op = outp + (u64)bcl*32768;
                a0 += ap[(u64)v*64 + l] + bia;
                a1 += ap[(u64)v*64 + l + 1] + bia;
                a2 += ap[(u64)(v+8)*64 + l] + bia;
                a3 += ap[(u64)(v+8)*64 + l + 1] + bia;
                if (l < 58)     op[(u64)v*64 + l + 6]       = a0;
                if (l + 1 < 58) op[(u64)v*64 + l + 7]       = a1;
                if (l < 58)     op[(u64)(v+8)*64 + l + 6]   = a2;
                if (l + 1 < 58) op[(u64)(v+8)*64 + l + 7]   = a3;
            }
        }
    }
}

__global__ void k_zeropad(float* __restrict__ outp){
    int i = blockIdx.x*256 + threadIdx.x;
    if (i < 8*64*512*6){
        int row = i / 6, t = i - row*6;
        outp[(u64)row*64 + t] = 0.f;
    }
}

// ---------------------------------------------------------------------------
extern "C" void kernel_launch(void* const* d_in, const int* in_sizes, int n_in,
                              void* d_out, int out_size){
    (void)in_sizes; (void)n_in; (void)out_size;
    const float* x   = (const float*)d_in[0];
    const float* adj = (const float*)d_in[1];
    float* out = (float*)d_out;

    // allow >48KB dynamic smem for the node kernels (idempotent)
    cudaFuncSetAttribute(k_node_mma<0>, cudaFuncAttributeMaxDynamicSharedMemorySize, NODE_SMEM);
    cudaFuncSetAttribute(k_node_mma<1>, cudaFuncAttributeMaxDynamicSharedMemorySize, NODE_SMEM);
    cudaFuncSetAttribute(k_node_mma<2>, cudaFuncAttributeMaxDynamicSharedMemorySize, NODE_SMEM);

    k_deg  <<<512, 256>>>(adj);
    k_norm <<<512, 256>>>(adj);
    k_prepA<<<512, 256>>>();
    k_prep<<<64, 256>>>(
        (const float*)d_in[ 2], (const float*)d_in[ 3], (const float*)d_in[ 4], (const float*)d_in[ 5],
        (const float*)d_in[ 6], (const float*)d_in[ 7], (const float*)d_in[ 8], (const float*)d_in[ 9],
        (const float*)d_in[10], (const float*)d_in[11], (const float*)d_in[12], (const float*)d_in[13],
        (const float*)d_in[14], (const float*)d_in[15], (const float*)d_in[16], (const float*)d_in[17],
        (const float*)d_in[18], (const float*)d_in[19], (const float*)d_in[20], (const float*)d_in[21]);

    k_fused<<<4096, 128>>>(x);

    // Horner: branch0 seed slot 0 (q4), branch1 seed slot 6 (q9);
    // merged launches run both branches via gridDim.z = 2.
    dim3 ng3(256, 4, 2);
    k_node_mma<0><<<ng3, 256, NODE_SMEM>>>(0, 3, 0, 2, nullptr);   // step 0
    k_node_mma<0><<<ng3, 256, NODE_SMEM>>>(0, 2, 2, 4, nullptr);   // step 1
    k_node_mma<0><<<ng3, 256, NODE_SMEM>>>(0, 1, 4, 2, nullptr);   // step 2
    dim3 ng(256, 4, 1);
    k_node_mma<1><<<ng, 256, NODE_SMEM>>>(0, 0, 2, 0, nullptr);    // b0 final -> ACC
    k_node_mma<2><<<ng, 256, NODE_SMEM>>>(1, 5, 8, 0, out);        // b1 final -> out

    k_zeropad<<<6144, 256>>>(out);
}

// round 16
// speedup vs baseline: 1.3030x; 1.0390x over previous
#include <cuda_runtime.h>
#include <cuda_bf16.h>

typedef unsigned long long u64;
typedef unsigned int u32;

// ---------------------------------------------------------------------------
// Shapes: B=8, C=64, N=512, T=64, valid L=58 (stored padded to 64).
// fp32 pool: q0..q9 (ids 0-9; 4 and 9 unused as fp32), ACC=12.
// bf16 state pool slots (BUFSZ each):
//   0/1 seed1(q4) hi/lo, 2/3 & 4/5 branch0 ping-pong,
//   6/7 seed2(q9) hi/lo, 8/9 & 10/11 branch1 ping-pong.
// bf16 state layout (SWIZZLED, chunk-major; see boff()):
//   bc*32768 + (n>>5)*2048 + (n&31)*64 + (((l>>3)^(n&7))<<3) + (l&7)
//   -> each (bc, 32-node chunk) is a contiguous 4KB block (cp.async.bulk src)
//      and ldmatrix.trans on the copied block is bank-conflict-free.
// A' layout: [asel][kchunk][v][32k], in-chunk unit swizzle ^((v>>1)&3):
//   contiguous 8KB per (kchunk, 128-row v-tile); 64B-row ldmatrix conflict-free.
// Node step: r' = q + d∘r + A'·r, d = diag(M)-1 exact fp32 in epilogue,
// A' = M - diag(M) (entries ~4e-3, bf16), ONE MMA product A'h·rh.
// ---------------------------------------------------------------------------
#define BUFSZ (8ULL*64ULL*512ULL*64ULL)

__device__ float g_pool[13ULL*BUFSZ];
__device__ __align__(16) __nv_bfloat16 g_bf[12ULL*BUFSZ];
__device__ __align__(16) __nv_bfloat16 g_Abf[2ULL*262144];
__device__ float g_dA[2*512];                  // diag(M)-1 per branch

__device__ float g_An [512*512];   // [w][v] = M1[v][w]
__device__ float g_AnT[512*512];   // [w][v] = M2[v][w]
__device__ float g_rd1[512], g_rd2[512];
__device__ __nv_bfloat16 g_W7h[128*448];   // [o][kd] hi
__device__ __nv_bfloat16 g_W7l[128*448];   // [o][kd] lo
__device__ float g_b7[128];
__device__ __nv_bfloat16 g_Wqh[10*64*64];  // [m][out][in] hi
__device__ __nv_bfloat16 g_Wql[10*64*64];  // [m][out][in] lo
__device__ float g_bias[64];

// ---------------------------------------------------------------------------
// helpers
// ---------------------------------------------------------------------------
__device__ __forceinline__ u32 smem_u32(const void* p){
    u32 a;
    asm("{ .reg .u64 t; cvta.to.shared.u64 t, %1; cvt.u32.u64 %0, t; }" : "=r"(a) : "l"(p));
    return a;
}
__device__ __forceinline__ void split2(float a0, float a1, u32& hi, u32& lo){
    __nv_bfloat16 h0 = __float2bfloat16(a0);
    __nv_bfloat16 h1 = __float2bfloat16(a1);
    float r0 = a0 - __bfloat162float(h0);
    float r1 = a1 - __bfloat162float(h1);
    union { __nv_bfloat162 v; u32 u; } ch, cl;
    ch.v = __halves2bfloat162(h0, h1);
    cl.v = __halves2bfloat162(__float2bfloat16(r0), __float2bfloat16(r1));
    hi = ch.u; lo = cl.u;
}
__device__ __forceinline__ float2 bf2f2(u32 u){
    union { u32 u; __nv_bfloat162 v; } c; c.u = u;
    return __bfloat1622float2(c.v);
}
// swizzled bf16-state element offset (l must address pairs with l even for u32 IO)
__device__ __forceinline__ u64 boff(int bc, int n, int l){
    return (u64)bc*32768 + (u64)((n>>5)*2048 + (n&31)*64
         + ((((l>>3) ^ (n&7)))<<3) + (l&7));
}

// ---------------------------------------------------------------------------
// mma.sync / ldmatrix / bulk-copy wrappers (<= sm_90 PTX, legal on compute_103)
// ---------------------------------------------------------------------------
__device__ __forceinline__ void mma16816(float* c, const u32* a, u32 b0, u32 b1){
    asm volatile(
        "mma.sync.aligned.m16n8k16.row.col.f32.bf16.bf16.f32 "
        "{%0,%1,%2,%3}, {%4,%5,%6,%7}, {%8,%9}, {%0,%1,%2,%3};"
        : "+f"(c[0]), "+f"(c[1]), "+f"(c[2]), "+f"(c[3])
        : "r"(a[0]), "r"(a[1]), "r"(a[2]), "r"(a[3]), "r"(b0), "r"(b1));
}
__device__ __forceinline__ void ldmA(u32* r, u32 addr){
    asm volatile("ldmatrix.sync.aligned.m8n8.x4.shared.b16 {%0,%1,%2,%3}, [%4];"
        : "=r"(r[0]), "=r"(r[1]), "=r"(r[2]), "=r"(r[3]) : "r"(addr));
}
__device__ __forceinline__ void ldmBT(u32* r, u32 addr){
    asm volatile("ldmatrix.sync.aligned.m8n8.x4.trans.shared.b16 {%0,%1,%2,%3}, [%4];"
        : "=r"(r[0]), "=r"(r[1]), "=r"(r[2]), "=r"(r[3]) : "r"(addr));
}
__device__ __forceinline__ void bulkcp(u32 dst, const void* src, u32 bytes, u32 mbar){
    asm volatile(
        "cp.async.bulk.shared::cluster.global.mbarrier::complete_tx::bytes "
        "[%0], [%1], %2, [%3];"
        :: "r"(dst), "l"(src), "r"(bytes), "r"(mbar) : "memory");
}
__device__ __forceinline__ void mbar_init(u32 mb, u32 cnt){
    asm volatile("mbarrier.init.shared.b64 [%0], %1;" :: "r"(mb), "r"(cnt) : "memory");
}
__device__ __forceinline__ void mbar_expect(u32 mb, u32 bytes){
    asm volatile("mbarrier.arrive.expect_tx.shared.b64 _, [%0], %1;"
        :: "r"(mb), "r"(bytes) : "memory");
}
__device__ __forceinline__ void mbar_wait(u32 mbar, u32 parity){
    asm volatile(
        "{\n\t.reg .pred P;\n\t"
        "W%=:\n\t"
        "mbarrier.try_wait.parity.acquire.cta.shared::cta.b64 P, [%0], %1, 0x989680;\n\t"
        "@P bra.uni D%=;\n\t"
        "bra.uni W%=;\n\t"
        "D%=:\n\t}"
        :: "r"(mbar), "r"(parity) : "memory");
}

// ---------------------------------------------------------------------------
// degrees + normalized adjacencies
// ---------------------------------------------------------------------------
__global__ void k_deg(const float* __restrict__ adj){
    int v = blockIdx.x, tid = threadIdx.x;
    float s1 = 0.f, s2 = 0.f;
    for (int w = tid; w < 512; w += 256){
        s1 += adj[v*512 + w];
        s2 += adj[w*512 + v];
    }
    __shared__ float r1[256], r2[256];
    r1[tid] = s1; r2[tid] = s2;
    __syncthreads();
    for (int s = 128; s > 0; s >>= 1){
        if (tid < s){ r1[tid] += r1[tid+s]; r2[tid] += r2[tid+s]; }
        __syncthreads();
    }
    if (tid == 0){
        g_rd1[v] = rsqrtf(r1[0] + 1.f);
        g_rd2[v] = rsqrtf(r2[0] + 1.f);
    }
}

__global__ void k_norm(const float* __restrict__ adj){
    int w = blockIdx.x;
    float dw1 = g_rd1[w], dw2 = g_rd2[w];
    for (int v = threadIdx.x; v < 512; v += 256){
        float e = (v == w) ? 1.f : 0.f;
        g_An [w*512 + v] = g_rd1[v] * (adj[v*512 + w] + e) * dw1;
        g_AnT[w*512 + v] = g_rd2[v] * (adj[w*512 + v] + e) * dw2;
    }
}

// A' = M - diag(M) bf16 in bulk-copy layout [asel][kc][v][32 swizzled];
// d = diag(M) - 1 in fp32.
__global__ void k_prepA(){
    int v = blockIdx.x;
    for (int w = threadIdx.x; w < 512; w += 256){
        float a1 = g_An [w*512 + v];
        float a2 = g_AnT[w*512 + v];
        if (w == v){
            g_dA[v]       = a1 - 1.f;
            g_dA[512 + v] = a2 - 1.f;
            a1 = 0.f; a2 = 0.f;
        }
        int kc = w >> 5, kk = w & 31;
        int p = ((((kk >> 3) ^ ((v >> 1) & 3))) << 3) + (kk & 7);
        u64 off = (u64)kc*16384 + (u64)v*32 + p;
        g_Abf[off]          = __float2bfloat16(a1);
        g_Abf[262144 + off] = __float2bfloat16(a2);
    }
}

// ---------------------------------------------------------------------------
// prep: pad inception weights to k=7 (windows end at l+6), build Horner W'_j.
// ---------------------------------------------------------------------------
__global__ void k_prep(const float* i1w0,const float* i1b0,const float* i1w1,const float* i1b1,
                       const float* i1w2,const float* i1b2,const float* i1w3,const float* i1b3,
                       const float* i2w0,const float* i2b0,const float* i2w1,const float* i2b1,
                       const float* i2w2,const float* i2b2,const float* i2w3,const float* i2b3,
                       const float* m1w,const float* m1b,const float* m2w,const float* m2b){
    int g0 = blockIdx.x*256 + threadIdx.x, gstr = gridDim.x*256;
    const float* WS[8] = {i1w0,i1w1,i1w2,i1w3,i2w0,i2w1,i2w2,i2w3};
    const float* BS[8] = {i1b0,i1b1,i1b2,i1b3,i2b0,i2b1,i2b2,i2b3};
    const int KERN[4] = {2,3,6,7};

    for (int idx = g0; idx < 128*448; idx += gstr){
        int o = idx / 448, kd = idx - o*448;
        int c = kd / 7, tau = kd - c*7;
        int br = o >> 6, j = (o >> 4) & 3, oc = o & 15;
        int k = KERN[j];
        int t = tau - (7 - k);
        float v = (t >= 0) ? WS[br*4 + j][(oc*64 + c)*k + t] : 0.f;
        __nv_bfloat16 h = __float2bfloat16(v);
        g_W7h[idx] = h;
        g_W7l[idx] = __float2bfloat16(v - __bfloat162float(h));
    }
    for (int idx = g0; idx < 128; idx += gstr){
        int br = idx >> 6, j = (idx >> 4) & 3, oc = idx & 15;
        g_b7[idx] = BS[br*4 + j][oc];
    }
    for (int idx = g0; idx < 64; idx += gstr)
        g_bias[idx] = m1b[idx] + m2b[idx];

    const float COEF[5][5] = {
        {1.f, 1.f,      1.f,      1.f,      1.f     },
        {0.f, 1.f/3.f,  2.f/3.f,  1.f,      1.f     },
        {0.f, 0.f,      1.f/3.f,  1.f/3.f,  0.5f    },
        {0.f, 0.f,      0.f,      1.f/3.f,  1.f/6.f },
        {0.f, 0.f,      0.f,      0.f,      1.f/24.f}};
    for (int idx = g0; idx < 10*4096; idx += gstr){
        int m = idx >> 12, cp = (idx >> 6) & 63, c = idx & 63;
        int j = m % 5;
        const float* mw = (m < 5) ? m1w : m2w;
        float s = 0.f;
#pragma unroll
        for (int g = 0; g < 5; ++g)
            s += COEF[j][g] * mw[c*320 + g*64 + cp];
        __nv_bfloat16 h = __float2bfloat16(s);
        int widx = (m << 12) + (c << 6) + cp;   // [m][out][in]
        g_Wqh[widx] = h;
        g_Wql[widx] = __float2bfloat16(s - __bfloat162float(h));
    }
}

// ---------------------------------------------------------------------------
// FUSED inception + gate + qgen, all tensor-core (mma.sync split-bf16).
// (unchanged except seed epilogue writes use the swizzled bf16-state layout)
// ---------------------------------------------------------------------------
__global__ __launch_bounds__(128) void k_fused(const float* __restrict__ x){
    __shared__ __align__(16) char sm[38912];
    __nv_bfloat16* sAh = (__nv_bfloat16*)(sm);            // [128][40]
    __nv_bfloat16* sAl = (__nv_bfloat16*)(sm + 10240);    // [128][40]
    __nv_bfloat16* sBh = (__nv_bfloat16*)(sm + 20480);    // [32][72]
    __nv_bfloat16* sBl = (__nv_bfloat16*)(sm + 25088);    // [32][72]
    float*         sG  = (float*)(sm);                    // [64][72] fp32
    __nv_bfloat16* sWh = (__nv_bfloat16*)(sm);            // [64][72]
    __nv_bfloat16* sWl = (__nv_bfloat16*)(sm + 9216);     // [64][72]
    __nv_bfloat16* sHh = (__nv_bfloat16*)(sm + 20480);    // [64][72]
    __nv_bfloat16* sHl = (__nv_bfloat16*)(sm + 29696);    // [64][72]

    int bn = blockIdx.x;
    int b = bn >> 9, n = bn & 511;
    int tid = threadIdx.x, lane = tid & 31, wid = tid >> 5;
    const float* xb = x + (u64)b*64*32768 + (u64)n*64;

    u32 uAh = smem_u32(sAh), uAl = smem_u32(sAl);
    u32 uBh = smem_u32(sBh), uBl = smem_u32(sBl);
    u32 uWh = smem_u32(sWh), uWl = smem_u32(sWl);
    u32 uHh = smem_u32(sHh), uHl = smem_u32(sHl);

    float acc[2][8][4];
#pragma unroll
    for (int m = 0; m < 2; ++m)
#pragma unroll
        for (int j = 0; j < 8; ++j)
#pragma unroll
            for (int e = 0; e < 4; ++e) acc[m][j][e] = 0.f;

    for (int kc = 0; kc < 14; ++kc){
        int w0 = kc*32;
#pragma unroll
        for (int i = 0; i < 4; ++i){
            int idx = i*128 + tid;
            int row = idx >> 2, seg = idx & 3;
            *(uint4*)(sAh + row*40 + seg*8) = *(const uint4*)(g_W7h + row*448 + w0 + seg*8);
            *(uint4*)(sAl + row*40 + seg*8) = *(const uint4*)(g_W7l + row*448 + w0 + seg*8);
        }
#pragma unroll
        for (int i = 0; i < 8; ++i){
            int idx = i*128 + tid;
            int row = idx >> 5, lp = idx & 31, l = lp*2;
            int kd = w0 + row;
            int c = kd / 7, tau = kd - c*7;
            int t = l + tau;
            float v0 = (t < 64) ? xb[(u64)c*32768 + t] : 0.f;
            float v1 = (t + 1 < 64) ? xb[(u64)c*32768 + t + 1] : 0.f;
            u32 h, lo; split2(v0, v1, h, lo);
            *(u32*)(sBh + row*72 + l) = h;
            *(u32*)(sBl + row*72 + l) = lo;
        }
        __syncthreads();
#pragma unroll
        for (int ks = 0; ks < 32; ks += 16){
            u32 ah[2][4], al[2][4];
            int arow = lane & 15, acol = ks + (lane >> 4)*8;
#pragma unroll
            for (int m = 0; m < 2; ++m){
                u32 ao = (u32)((wid*32 + m*16 + arow)*40 + acol)*2;
                ldmA(ah[m], uAh + ao);
                ldmA(al[m], uAl + ao);
            }
            int brow = ks + (lane & 15), bcol = (lane >> 4)*8;
#pragma unroll
            for (int g = 0; g < 4; ++g){
                u32 bh[4], bl[4];
                u32 bo = (u32)(brow*72 + g*16 + bcol)*2;
                ldmBT(bh, uBh + bo);
                ldmBT(bl, uBl + bo);
#pragma unroll
                for (int m = 0; m < 2; ++m){
#pragma unroll
                    for (int h = 0; h < 2; ++h){
                        float* c = acc[m][g*2 + h];
                        mma16816(c, ah[m], bh[2*h], bh[2*h+1]);
                        mma16816(c, ah[m], bl[2*h], bl[2*h+1]);
                        mma16816(c, al[m], bh[2*h], bh[2*h+1]);
                    }
                }
            }
        }
        __syncthreads();
    }

    int lbase = (lane & 3)*2, rbase = lane >> 2;
    if (wid >= 2){
#pragma unroll
        for (int m = 0; m < 2; ++m){
            int o = wid*32 + m*16 + rbase;
#pragma unroll
            for (int jj = 0; jj < 8; ++jj){
                int l = jj*8 + lbase;
                float* c = acc[m][jj];
                float b0 = g_b7[o], b1 = g_b7[o + 8];
                float2 g0, g1;
                g0.x = 1.f/(1.f + expf(-(c[0] + b0)));
                g0.y = 1.f/(1.f + expf(-(c[1] + b0)));
                g1.x = 1.f/(1.f + expf(-(c[2] + b1)));
                g1.y = 1.f/(1.f + expf(-(c[3] + b1)));
                *(float2*)(sG + (o - 64)*72 + l) = g0;
                *(float2*)(sG + (o - 64 + 8)*72 + l) = g1;
            }
        }
    }
    __syncthreads();
    if (wid < 2){
#pragma unroll
        for (int m = 0; m < 2; ++m){
            int c0 = wid*32 + m*16 + rbase;
#pragma unroll
            for (int jj = 0; jj < 8; ++jj){
                int l = jj*8 + lbase;
                float* c = acc[m][jj];
                float b0 = g_b7[c0], b1 = g_b7[c0 + 8];
                float2 ga = *(const float2*)(sG + c0*72 + l);
                float2 gb = *(const float2*)(sG + (c0 + 8)*72 + l);
                float h0 = tanhf(c[0] + b0) * ga.x;
                float h1 = tanhf(c[1] + b0) * ga.y;
                float h2 = tanhf(c[2] + b1) * gb.x;
                float h3 = tanhf(c[3] + b1) * gb.y;
                u32 ph0, pl0, ph1, pl1;
                split2(h0, h1, ph0, pl0);
                split2(h2, h3, ph1, pl1);
                *(u32*)(sHh + c0*72 + l) = ph0;
                *(u32*)(sHl + c0*72 + l) = pl0;
                *(u32*)(sHh + (c0 + 8)*72 + l) = ph1;
                *(u32*)(sHl + (c0 + 8)*72 + l) = pl1;
            }
        }
    }

    for (int m = 0; m < 10; ++m){
        __syncthreads();
#pragma unroll
        for (int i = 0; i < 4; ++i){
            int idx = i*128 + tid;
            int row = idx >> 3, seg = idx & 7;
            *(uint4*)(sWh + row*72 + seg*8) = *(const uint4*)(g_Wqh + m*4096 + row*64 + seg*8);
            *(uint4*)(sWl + row*72 + seg*8) = *(const uint4*)(g_Wql + m*4096 + row*64 + seg*8);
        }
        __syncthreads();

        float a2[8][4];
#pragma unroll
        for (int j = 0; j < 8; ++j)
#pragma unroll
            for (int e = 0; e < 4; ++e) a2[j][e] = 0.f;

#pragma unroll
        for (int ks = 0; ks < 64; ks += 16){
            u32 ah[4], al[4];
            u32 ao = (u32)((wid*16 + (lane & 15))*72 + ks + (lane >> 4)*8)*2;
            ldmA(ah, uWh + ao);
            ldmA(al, uWl + ao);
            int brow = ks + (lane & 15), bcol = (lane >> 4)*8;
#pragma unroll
            for (int g = 0; g < 4; ++g){
                u32 bh[4], bl[4];
                u32 bo = (u32)(brow*72 + g*16 + bcol)*2;
                ldmBT(bh, uHh + bo);
                ldmBT(bl, uHl + bo);
#pragma unroll
                for (int h = 0; h < 2; ++h){
                    float* c = a2[g*2 + h];
                    mma16816(c, ah, bh[2*h], bh[2*h+1]);
                    mma16816(c, ah, bl[2*h], bl[2*h+1]);
                    mma16816(c, al, bh[2*h], bh[2*h+1]);
                }
            }
        }

        int cp = wid*16 + rbase;
        if (m == 4 || m == 9){
            __nv_bfloat16* wh = g_bf + (u64)(m == 4 ? 0 : 6)*BUFSZ;
            __nv_bfloat16* wl = wh + BUFSZ;
            int bcA = b*64 + cp, bcB = bcA + 8;
#pragma unroll
            for (int jj = 0; jj < 8; ++jj){
                int l = jj*8 + lbase;
                float* c = a2[jj];
                u32 h0, l0, h1, l1;
                split2(c[0], c[1], h0, l0);
                split2(c[2], c[3], h1, l1);
                u64 o1 = boff(bcA, n, l), o2 = boff(bcB, n, l);
                *(u32*)(wh + o1) = h0;
                *(u32*)(wl + o1) = l0;
                *(u32*)(wh + o2) = h1;
                *(u32*)(wl + o2) = l1;
            }
        } else {
            float* dst = g_pool + (u64)m*BUFSZ;
            u64 eoff0 = ((u64)(b*64 + cp)*512 + n)*64;
            u64 eoff1 = ((u64)(b*64 + cp + 8)*512 + n)*64;
#pragma unroll
            for (int jj = 0; jj < 8; ++jj){
                int l = jj*8 + lbase;
                float* c = a2[jj];
                *(float2*)(dst + eoff0 + l) = make_float2(c[0], c[1]);
                *(float2*)(dst + eoff1 + l) = make_float2(c[2], c[3]);
            }
        }
    }
}

// ---------------------------------------------------------------------------
// tensor-core node step: r' = q + d∘r + A'·r  (ONE product A'h·rh)
// 256 threads, tile 128v x 128l (bc0=2*bx; warp wx selects bc, wy the v rows).
// 3-stage pipeline, cp.async.bulk (A 8KB + 2x B 4KB per chunk, ONE issuing
// thread) with per-stage mbarrier; one __syncthreads per chunk.
// Stage layout (16384B): [A 8192][B_bc0 4096][B_bc1 4096].
// MODE 0: write r' bf16 hi/lo (swizzled); MODE 1: fp32 ACC; MODE 2: output.
// ---------------------------------------------------------------------------
#define NODE_SST 16384
#define NODE_SMEM (3*NODE_SST)

__device__ __forceinline__ void node_issue(u32 sb, u32 mb,
        const __nv_bfloat16* Ah, const __nv_bfloat16* Bh0,
        int kc, int v0c, int bc0){
    mbar_expect(mb, 16384u);
    bulkcp(sb,         Ah  + (u64)kc*16384 + (u64)v0c*32,        8192, mb);
    bulkcp(sb + 8192,  Bh0 + (u64)bc0*32768 + (u64)kc*2048,      4096, mb);
    bulkcp(sb + 12288, Bh0 + (u64)(bc0+1)*32768 + (u64)kc*2048,  4096, mb);
}

template<int MODE>
__global__ __launch_bounds__(256, 2)
void k_node_mma(int asel, int qid, int bslot, int wslot, float* __restrict__ outp){
    extern __shared__ __align__(16) char smn[];
    __shared__ __align__(8) u64 s_mb[3];
    u32 base = smem_u32(smn);

    int z = blockIdx.z;
    asel += z; qid += 5*z; bslot += 6*z; wslot += 6*z;

    int tid = threadIdx.x, lane = tid & 31, wid = tid >> 5;
    int wy = wid & 3, wx = wid >> 2;
    int bc0 = blockIdx.x*2, v0c = blockIdx.y << 7;

    const __nv_bfloat16* Ah  = g_Abf + (u64)asel*262144;
    const __nv_bfloat16* Bh0 = g_bf + (u64)bslot*BUFSZ;
    const float* dvec = g_dA + asel*512;

    if (tid == 0){
        mbar_init(smem_u32(&s_mb[0]), 1);
        mbar_init(smem_u32(&s_mb[1]), 1);
        mbar_init(smem_u32(&s_mb[2]), 1);
    }
    __syncthreads();
    if (tid == 0){
        node_issue(base,            smem_u32(&s_mb[0]), Ah, Bh0, 0, v0c, bc0);
        node_issue(base + NODE_SST, smem_u32(&s_mb[1]), Ah, Bh0, 1, v0c, bc0);
    }

    float acc[2][8][4];
#pragma unroll
    for (int m = 0; m < 2; ++m)
#pragma unroll
        for (int j = 0; j < 8; ++j)
#pragma unroll
            for (int e = 0; e < 4; ++e) acc[m][j][e] = 0.f;

    int st = 0, pst = 2;
    for (int kc = 0; kc < 16; ++kc){
        mbar_wait(smem_u32(&s_mb[st]), (kc/3)&1);
        __syncthreads();   // all warps finished MMA on stage (kc-1)%3 == pst
        if (tid == 0 && kc + 2 < 16)
            node_issue(base + pst*NODE_SST, smem_u32(&s_mb[pst]),
                       Ah, Bh0, kc + 2, v0c, bc0);

        u32 sb = base + st*NODE_SST;
        u32 uA = sb, uB = sb + 8192 + (wx << 12);
#pragma unroll
        for (int ks = 0; ks < 32; ks += 16){
            u32 ah[2][4];
            int arow = lane & 15;
            int uk = (ks >> 3) + (lane >> 4);          // 0..3 (16B unit in k)
#pragma unroll
            for (int m = 0; m < 2; ++m){
                int row = wy*32 + m*16 + arow;
                u32 ao = (u32)(row*64 + ((uk ^ ((row >> 1) & 3)) << 4));
                ldmA(ah[m], uA + ao);
            }
            int brow = ks + (lane & 15);
            int sbz = brow & 7;
#pragma unroll
            for (int g = 0; g < 4; ++g){
                u32 bh[4];
                int un = (2*g + (lane >> 4)) ^ sbz;
                ldmBT(bh, uB + (u32)(brow*128 + (un << 4)));
#pragma unroll
                for (int m = 0; m < 2; ++m){
#pragma unroll
                    for (int h = 0; h < 2; ++h){
                        float* c = acc[m][g*2 + h];
                        mma16816(c, ah[m], bh[2*h], bh[2*h+1]);
                    }
                }
            }
        }
        st = (st == 2) ? 0 : st + 1;
        pst = (pst == 2) ? 0 : pst + 1;
    }

    int lbase = (lane & 3)*2, rbase = lane >> 2;
    int bcl = bc0 + wx;
    const float* qp = g_pool + (u64)qid*BUFSZ + (u64)bcl*32768;
    const __nv_bfloat16* rhp = g_bf + (u64)bslot*BUFSZ;
    const __nv_bfloat16* rlp = rhp + BUFSZ;
#pragma unroll
    for (int m = 0; m < 2; ++m){
        int v = v0c + wy*32 + m*16 + rbase;
        float d0 = dvec[v], d1 = dvec[v + 8];
#pragma unroll
        for (int jj = 0; jj < 8; ++jj){
            int l = jj*8 + lbase;
            float* c = acc[m][jj];
            float2 q0 = *(const float2*)(qp + (u64)v*64 + l);
            float2 q1 = *(const float2*)(qp + (u64)(v+8)*64 + l);
            u64 o1 = boff(bcl, v, l), o2 = boff(bcl, v + 8, l);
            float2 r0h = bf2f2(*(const u32*)(rhp + o1));
            float2 r0l = bf2f2(*(const u32*)(rlp + o1));
            float2 r1h = bf2f2(*(const u32*)(rhp + o2));
            float2 r1l = bf2f2(*(const u32*)(rlp + o2));
            float a0 = c[0] + q0.x + d0*(r0h.x + r0l.x);
            float a1 = c[1] + q0.y + d0*(r0h.y + r0l.y);
            float a2 = c[2] + q1.x + d1*(r1h.x + r1l.x);
            float a3 = c[3] + q1.y + d1*(r1h.y + r1l.y);
            if (MODE == 0){
                __nv_bfloat16* wh = g_bf + (u64)wslot*BUFSZ;
                __nv_bfloat16* wl = wh + BUFSZ;
                u32 h0, l0, h1, l1;
                split2(a0, a1, h0, l0);
                split2(a2, a3, h1, l1);
                u64 w1 = boff(bcl, v, l), w2 = boff(bcl, v + 8, l);
                *(u32*)(wh + w1) = h0;
                *(u32*)(wl + w1) = l0;
                *(u32*)(wh + w2) = h1;
                *(u32*)(wl + w2) = l1;
            } else if (MODE == 1){
                float* op = g_pool + 12ULL*BUFSZ + (u64)bcl*32768;
                *(float2*)(op + (u64)v*64 + l) = make_float2(a0, a1);
                *(float2*)(op + (u64)(v+8)*64 + l) = make_float2(a2, a3);
            } else {
                const float* ap = g_pool + 12ULL*BUFSZ + (u64)bcl*32768;
                float bia = g_bias[bcl & 63];
                float* op = outp + (u64)bcl*32768;
                a0 += ap[(u64)v*64 + l] + bia;
                a1 += ap[(u64)v*64 + l + 1] + bia;
                a2 += ap[(u64)(v+8)*64 + l] + bia;
                a3 += ap[(u64)(v+8)*64 + l + 1] + bia;
                if (l < 58)     op[(u64)v*64 + l + 6]       = a0;
                if (l + 1 < 58) op[(u64)v*64 + l + 7]       = a1;
                if (l < 58)     op[(u64)(v+8)*64 + l + 6]   = a2;
                if (l + 1 < 58) op[(u64)(v+8)*64 + l + 7]   = a3;
            }
        }
    }
}

__global__ void k_zeropad(float* __restrict__ outp){
    int i = blockIdx.x*256 + threadIdx.x;
    if (i < 8*64*512*6){
        int row = i / 6, t = i - row*6;
        outp[(u64)row*64 + t] = 0.f;
    }
}

// ---------------------------------------------------------------------------
extern "C" void kernel_launch(void* const* d_in, const int* in_sizes, int n_in,
                              void* d_out, int out_size){
    (void)in_sizes; (void)n_in; (void)out_size;
    const float* x   = (const float*)d_in[0];
    const float* adj = (const float*)d_in[1];
    float* out = (float*)d_out;

    cudaFuncSetAttribute(k_node_mma<0>, cudaFuncAttributeMaxDynamicSharedMemorySize, NODE_SMEM);
    cudaFuncSetAttribute(k_node_mma<1>, cudaFuncAttributeMaxDynamicSharedMemorySize, NODE_SMEM);
    cudaFuncSetAttribute(k_node_mma<2>, cudaFuncAttributeMaxDynamicSharedMemorySize, NODE_SMEM);

    k_deg  <<<512, 256>>>(adj);
    k_norm <<<512, 256>>>(adj);
    k_prepA<<<512, 256>>>();
    k_prep<<<64, 256>>>(
        (const float*)d_in[ 2], (const float*)d_in[ 3], (const float*)d_in[ 4], (const float*)d_in[ 5],
        (const float*)d_in[ 6], (const float*)d_in[ 7], (const float*)d_in[ 8], (const float*)d_in[ 9],
        (const float*)d_in[10], (const float*)d_in[11], (const float*)d_in[12], (const float*)d_in[13],
        (const float*)d_in[14], (const float*)d_in[15], (const float*)d_in[16], (const float*)d_in[17],
        (const float*)d_in[18], (const float*)d_in[19], (const float*)d_in[20], (const float*)d_in[21]);

    k_fused<<<4096, 128>>>(x);

    // Horner: branch0 seed slot 0 (q4), branch1 seed slot 6 (q9);
    // merged launches run both branches via gridDim.z = 2.
    dim3 ng3(256, 4, 2);
    k_node_mma<0><<<ng3, 256, NODE_SMEM>>>(0, 3, 0, 2, nullptr);   // step 0
    k_node_mma<0><<<ng3, 256, NODE_SMEM>>>(0, 2, 2, 4, nullptr);   // step 1
    k_node_mma<0><<<ng3, 256, NODE_SMEM>>>(0, 1, 4, 2, nullptr);   // step 2
    dim3 ng(256, 4, 1);
    k_node_mma<1><<<ng, 256, NODE_SMEM>>>(0, 0, 2, 0, nullptr);    // b0 final -> ACC
    k_node_mma<2><<<ng, 256, NODE_SMEM>>>(1, 5, 8, 0, out);        // b1 final -> out

    k_zeropad<<<6144, 256>>>(out);
}

// round 17
// speedup vs baseline: 1.3516x; 1.0373x over previous
#include <cuda_runtime.h>
#include <cuda_bf16.h>

typedef unsigned long long u64;
typedef unsigned int u32;

// ---------------------------------------------------------------------------
// Shapes: B=8, C=64, N=512, T=64, valid L=58 (stored padded to 64).
// fp32 pool: q0..q9 (ids 0-9; 4 and 9 unused as fp32), ACC=12.
// bf16 state pool slots (BUFSZ each):
//   0/1 seed1(q4) hi/lo, 2/3 & 4/5 branch0 ping-pong,
//   6/7 seed2(q9) hi/lo, 8/9 & 10/11 branch1 ping-pong.
// bf16 state layout (SWIZZLED, chunk-major; see boff()):
//   bc*32768 + (n>>5)*2048 + (n&31)*64 + (((l>>3)^(n&7))<<3) + (l&7)
// A' layout: [asel][kchunk][v][32k], in-chunk unit swizzle ^((v>>1)&3).
// Node step: r' = q + d∘r + A'·r, d = diag(M)-1 exact fp32 in epilogue,
// A' = M - diag(M) (entries ~4e-3, bf16), ONE MMA product A'h·rh.
// Node CTA: 128 threads, tile 64v x 128l, 3-stage bulk pipeline, 4 CTAs/SM.
// ---------------------------------------------------------------------------
#define BUFSZ (8ULL*64ULL*512ULL*64ULL)

__device__ float g_pool[13ULL*BUFSZ];
__device__ __align__(16) __nv_bfloat16 g_bf[12ULL*BUFSZ];
__device__ __align__(16) __nv_bfloat16 g_Abf[2ULL*262144];
__device__ float g_dA[2*512];                  // diag(M)-1 per branch

__device__ float g_An [512*512];   // [w][v] = M1[v][w]
__device__ float g_AnT[512*512];   // [w][v] = M2[v][w]
__device__ float g_rd1[512], g_rd2[512];
__device__ __nv_bfloat16 g_W7h[128*448];   // [o][kd] hi
__device__ __nv_bfloat16 g_W7l[128*448];   // [o][kd] lo
__device__ float g_b7[128];
__device__ __nv_bfloat16 g_Wqh[10*64*64];  // [m][out][in] hi
__device__ __nv_bfloat16 g_Wql[10*64*64];  // [m][out][in] lo
__device__ float g_bias[64];

// ---------------------------------------------------------------------------
// helpers
// ---------------------------------------------------------------------------
__device__ __forceinline__ u32 smem_u32(const void* p){
    u32 a;
    asm("{ .reg .u64 t; cvta.to.shared.u64 t, %1; cvt.u32.u64 %0, t; }" : "=r"(a) : "l"(p));
    return a;
}
__device__ __forceinline__ void split2(float a0, float a1, u32& hi, u32& lo){
    __nv_bfloat16 h0 = __float2bfloat16(a0);
    __nv_bfloat16 h1 = __float2bfloat16(a1);
    float r0 = a0 - __bfloat162float(h0);
    float r1 = a1 - __bfloat162float(h1);
    union { __nv_bfloat162 v; u32 u; } ch, cl;
    ch.v = __halves2bfloat162(h0, h1);
    cl.v = __halves2bfloat162(__float2bfloat16(r0), __float2bfloat16(r1));
    hi = ch.u; lo = cl.u;
}
__device__ __forceinline__ float2 bf2f2(u32 u){
    union { u32 u; __nv_bfloat162 v; } c; c.u = u;
    return __bfloat1622float2(c.v);
}
// swizzled bf16-state element offset
__device__ __forceinline__ u64 boff(int bc, int n, int l){
    return (u64)bc*32768 + (u64)((n>>5)*2048 + (n&31)*64
         + ((((l>>3) ^ (n&7)))<<3) + (l&7));
}

// ---------------------------------------------------------------------------
// mma.sync / ldmatrix / bulk-copy wrappers (<= sm_90 PTX, legal on compute_103)
// ---------------------------------------------------------------------------
__device__ __forceinline__ void mma16816(float* c, const u32* a, u32 b0, u32 b1){
    asm volatile(
        "mma.sync.aligned.m16n8k16.row.col.f32.bf16.bf16.f32 "
        "{%0,%1,%2,%3}, {%4,%5,%6,%7}, {%8,%9}, {%0,%1,%2,%3};"
        : "+f"(c[0]), "+f"(c[1]), "+f"(c[2]), "+f"(c[3])
        : "r"(a[0]), "r"(a[1]), "r"(a[2]), "r"(a[3]), "r"(b0), "r"(b1));
}
__device__ __forceinline__ void ldmA(u32* r, u32 addr){
    asm volatile("ldmatrix.sync.aligned.m8n8.x4.shared.b16 {%0,%1,%2,%3}, [%4];"
        : "=r"(r[0]), "=r"(r[1]), "=r"(r[2]), "=r"(r[3]) : "r"(addr));
}
__device__ __forceinline__ void ldmBT(u32* r, u32 addr){
    asm volatile("ldmatrix.sync.aligned.m8n8.x4.trans.shared.b16 {%0,%1,%2,%3}, [%4];"
        : "=r"(r[0]), "=r"(r[1]), "=r"(r[2]), "=r"(r[3]) : "r"(addr));
}
__device__ __forceinline__ void bulkcp(u32 dst, const void* src, u32 bytes, u32 mbar){
    asm volatile(
        "cp.async.bulk.shared::cluster.global.mbarrier::complete_tx::bytes "
        "[%0], [%1], %2, [%3];"
        :: "r"(dst), "l"(src), "r"(bytes), "r"(mbar) : "memory");
}
__device__ __forceinline__ void mbar_init(u32 mb, u32 cnt){
    asm volatile("mbarrier.init.shared.b64 [%0], %1;" :: "r"(mb), "r"(cnt) : "memory");
}
__device__ __forceinline__ void mbar_expect(u32 mb, u32 bytes){
    asm volatile("mbarrier.arrive.expect_tx.shared.b64 _, [%0], %1;"
        :: "r"(mb), "r"(bytes) : "memory");
}
__device__ __forceinline__ void mbar_wait(u32 mbar, u32 parity){
    asm volatile(
        "{\n\t.reg .pred P;\n\t"
        "W%=:\n\t"
        "mbarrier.try_wait.parity.acquire.cta.shared::cta.b64 P, [%0], %1, 0x989680;\n\t"
        "@P bra.uni D%=;\n\t"
        "bra.uni W%=;\n\t"
        "D%=:\n\t}"
        :: "r"(mbar), "r"(parity) : "memory");
}

// ---------------------------------------------------------------------------
// degrees + normalized adjacencies
// ---------------------------------------------------------------------------
__global__ void k_deg(const float* __restrict__ adj){
    int v = blockIdx.x, tid = threadIdx.x;
    float s1 = 0.f, s2 = 0.f;
    for (int w = tid; w < 512; w += 256){
        s1 += adj[v*512 + w];
        s2 += adj[w*512 + v];
    }
    __shared__ float r1[256], r2[256];
    r1[tid] = s1; r2[tid] = s2;
    __syncthreads();
    for (int s = 128; s > 0; s >>= 1){
        if (tid < s){ r1[tid] += r1[tid+s]; r2[tid] += r2[tid+s]; }
        __syncthreads();
    }
    if (tid == 0){
        g_rd1[v] = rsqrtf(r1[0] + 1.f);
        g_rd2[v] = rsqrtf(r2[0] + 1.f);
    }
}

__global__ void k_norm(const float* __restrict__ adj){
    int w = blockIdx.x;
    float dw1 = g_rd1[w], dw2 = g_rd2[w];
    for (int v = threadIdx.x; v < 512; v += 256){
        float e = (v == w) ? 1.f : 0.f;
        g_An [w*512 + v] = g_rd1[v] * (adj[v*512 + w] + e) * dw1;
        g_AnT[w*512 + v] = g_rd2[v] * (adj[w*512 + v] + e) * dw2;
    }
}

// A' = M - diag(M) bf16 in bulk-copy layout [asel][kc][v][32 swizzled];
// d = diag(M) - 1 in fp32.
__global__ void k_prepA(){
    int v = blockIdx.x;
    for (int w = threadIdx.x; w < 512; w += 256){
        float a1 = g_An [w*512 + v];
        float a2 = g_AnT[w*512 + v];
        if (w == v){
            g_dA[v]       = a1 - 1.f;
            g_dA[512 + v] = a2 - 1.f;
            a1 = 0.f; a2 = 0.f;
        }
        int kc = w >> 5, kk = w & 31;
        int p = ((((kk >> 3) ^ ((v >> 1) & 3))) << 3) + (kk & 7);
        u64 off = (u64)kc*16384 + (u64)v*32 + p;
        g_Abf[off]          = __float2bfloat16(a1);
        g_Abf[262144 + off] = __float2bfloat16(a2);
    }
}

// ---------------------------------------------------------------------------
// prep: pad inception weights to k=7 (windows end at l+6), build Horner W'_j.
// ---------------------------------------------------------------------------
__global__ void k_prep(const float* i1w0,const float* i1b0,const float* i1w1,const float* i1b1,
                       const float* i1w2,const float* i1b2,const float* i1w3,const float* i1b3,
                       const float* i2w0,const float* i2b0,const float* i2w1,const float* i2b1,
                       const float* i2w2,const float* i2b2,const float* i2w3,const float* i2b3,
                       const float* m1w,const float* m1b,const float* m2w,const float* m2b){
    int g0 = blockIdx.x*256 + threadIdx.x, gstr = gridDim.x*256;
    const float* WS[8] = {i1w0,i1w1,i1w2,i1w3,i2w0,i2w1,i2w2,i2w3};
    const float* BS[8] = {i1b0,i1b1,i1b2,i1b3,i2b0,i2b1,i2b2,i2b3};
    const int KERN[4] = {2,3,6,7};

    for (int idx = g0; idx < 128*448; idx += gstr){
        int o = idx / 448, kd = idx - o*448;
        int c = kd / 7, tau = kd - c*7;
        int br = o >> 6, j = (o >> 4) & 3, oc = o & 15;
        int k = KERN[j];
        int t = tau - (7 - k);
        float v = (t >= 0) ? WS[br*4 + j][(oc*64 + c)*k + t] : 0.f;
        __nv_bfloat16 h = __float2bfloat16(v);
        g_W7h[idx] = h;
        g_W7l[idx] = __float2bfloat16(v - __bfloat162float(h));
    }
    for (int idx = g0; idx < 128; idx += gstr){
        int br = idx >> 6, j = (idx >> 4) & 3, oc = idx & 15;
        g_b7[idx] = BS[br*4 + j][oc];
    }
    for (int idx = g0; idx < 64; idx += gstr)
        g_bias[idx] = m1b[idx] + m2b[idx];

    const float COEF[5][5] = {
        {1.f, 1.f,      1.f,      1.f,      1.f     },
        {0.f, 1.f/3.f,  2.f/3.f,  1.f,      1.f     },
        {0.f, 0.f,      1.f/3.f,  1.f/3.f,  0.5f    },
        {0.f, 0.f,      0.f,      1.f/3.f,  1.f/6.f },
        {0.f, 0.f,      0.f,      0.f,      1.f/24.f}};
    for (int idx = g0; idx < 10*4096; idx += gstr){
        int m = idx >> 12, cp = (idx >> 6) & 63, c = idx & 63;
        int j = m % 5;
        const float* mw = (m < 5) ? m1w : m2w;
        float s = 0.f;
#pragma unroll
        for (int g = 0; g < 5; ++g)
            s += COEF[j][g] * mw[c*320 + g*64 + cp];
        __nv_bfloat16 h = __float2bfloat16(s);
        int widx = (m << 12) + (c << 6) + cp;   // [m][out][in]
        g_Wqh[widx] = h;
        g_Wql[widx] = __float2bfloat16(s - __bfloat162float(h));
    }
}

// ---------------------------------------------------------------------------
// FUSED inception + gate + qgen, all tensor-core (mma.sync split-bf16).
// ---------------------------------------------------------------------------
__global__ __launch_bounds__(128) void k_fused(const float* __restrict__ x){
    __shared__ __align__(16) char sm[38912];
    __nv_bfloat16* sAh = (__nv_bfloat16*)(sm);            // [128][40]
    __nv_bfloat16* sAl = (__nv_bfloat16*)(sm + 10240);    // [128][40]
    __nv_bfloat16* sBh = (__nv_bfloat16*)(sm + 20480);    // [32][72]
    __nv_bfloat16* sBl = (__nv_bfloat16*)(sm + 25088);    // [32][72]
    float*         sG  = (float*)(sm);                    // [64][72] fp32
    __nv_bfloat16* sWh = (__nv_bfloat16*)(sm);            // [64][72]
    __nv_bfloat16* sWl = (__nv_bfloat16*)(sm + 9216);     // [64][72]
    __nv_bfloat16* sHh = (__nv_bfloat16*)(sm + 20480);    // [64][72]
    __nv_bfloat16* sHl = (__nv_bfloat16*)(sm + 29696);    // [64][72]

    int bn = blockIdx.x;
    int b = bn >> 9, n = bn & 511;
    int tid = threadIdx.x, lane = tid & 31, wid = tid >> 5;
    const float* xb = x + (u64)b*64*32768 + (u64)n*64;

    u32 uAh = smem_u32(sAh), uAl = smem_u32(sAl);
    u32 uBh = smem_u32(sBh), uBl = smem_u32(sBl);
    u32 uWh = smem_u32(sWh), uWl = smem_u32(sWl);
    u32 uHh = smem_u32(sHh), uHl = smem_u32(sHl);

    float acc[2][8][4];
#pragma unroll
    for (int m = 0; m < 2; ++m)
#pragma unroll
        for (int j = 0; j < 8; ++j)
#pragma unroll
            for (int e = 0; e < 4; ++e) acc[m][j][e] = 0.f;

    for (int kc = 0; kc < 14; ++kc){
        int w0 = kc*32;
#pragma unroll
        for (int i = 0; i < 4; ++i){
            int idx = i*128 + tid;
            int row = idx >> 2, seg = idx & 3;
            *(uint4*)(sAh + row*40 + seg*8) = *(const uint4*)(g_W7h + row*448 + w0 + seg*8);
            *(uint4*)(sAl + row*40 + seg*8) = *(const uint4*)(g_W7l + row*448 + w0 + seg*8);
        }
#pragma unroll
        for (int i = 0; i < 8; ++i){
            int idx = i*128 + tid;
            int row = idx >> 5, lp = idx & 31, l = lp*2;
            int kd = w0 + row;
            int c = kd / 7, tau = kd - c*7;
            int t = l + tau;
            float v0 = (t < 64) ? xb[(u64)c*32768 + t] : 0.f;
            float v1 = (t + 1 < 64) ? xb[(u64)c*32768 + t + 1] : 0.f;
            u32 h, lo; split2(v0, v1, h, lo);
            *(u32*)(sBh + row*72 + l) = h;
            *(u32*)(sBl + row*72 + l) = lo;
        }
        __syncthreads();
#pragma unroll
        for (int ks = 0; ks < 32; ks += 16){
            u32 ah[2][4], al[2][4];
            int arow = lane & 15, acol = ks + (lane >> 4)*8;
#pragma unroll
            for (int m = 0; m < 2; ++m){
                u32 ao = (u32)((wid*32 + m*16 + arow)*40 + acol)*2;
                ldmA(ah[m], uAh + ao);
                ldmA(al[m], uAl + ao);
            }
            int brow = ks + (lane & 15), bcol = (lane >> 4)*8;
#pragma unroll
            for (int g = 0; g < 4; ++g){
                u32 bh[4], bl[4];
                u32 bo = (u32)(brow*72 + g*16 + bcol)*2;
                ldmBT(bh, uBh + bo);
                ldmBT(bl, uBl + bo);
#pragma unroll
                for (int m = 0; m < 2; ++m){
#pragma unroll
                    for (int h = 0; h < 2; ++h){
                        float* c = acc[m][g*2 + h];
                        mma16816(c, ah[m], bh[2*h], bh[2*h+1]);
                        mma16816(c, ah[m], bl[2*h], bl[2*h+1]);
                        mma16816(c, al[m], bh[2*h], bh[2*h+1]);
                    }
                }
            }
        }
        __syncthreads();
    }

    int lbase = (lane & 3)*2, rbase = lane >> 2;
    if (wid >= 2){
#pragma unroll
        for (int m = 0; m < 2; ++m){
            int o = wid*32 + m*16 + rbase;
#pragma unroll
            for (int jj = 0; jj < 8; ++jj){
                int l = jj*8 + lbase;
                float* c = acc[m][jj];
                float b0 = g_b7[o], b1 = g_b7[o + 8];
                float2 g0, g1;
                g0.x = 1.f/(1.f + expf(-(c[0] + b0)));
                g0.y = 1.f/(1.f + expf(-(c[1] + b0)));
                g1.x = 1.f/(1.f + expf(-(c[2] + b1)));
                g1.y = 1.f/(1.f + expf(-(c[3] + b1)));
                *(float2*)(sG + (o - 64)*72 + l) = g0;
                *(float2*)(sG + (o - 64 + 8)*72 + l) = g1;
            }
        }
    }
    __syncthreads();
    if (wid < 2){
#pragma unroll
        for (int m = 0; m < 2; ++m){
            int c0 = wid*32 + m*16 + rbase;
#pragma unroll
            for (int jj = 0; jj < 8; ++jj){
                int l = jj*8 + lbase;
                float* c = acc[m][jj];
                float b0 = g_b7[c0], b1 = g_b7[c0 + 8];
                float2 ga = *(const float2*)(sG + c0*72 + l);
                float2 gb = *(const float2*)(sG + (c0 + 8)*72 + l);
                float h0 = tanhf(c[0] + b0) * ga.x;
                float h1 = tanhf(c[1] + b0) * ga.y;
                float h2 = tanhf(c[2] + b1) * gb.x;
                float h3 = tanhf(c[3] + b1) * gb.y;
                u32 ph0, pl0, ph1, pl1;
                split2(h0, h1, ph0, pl0);
                split2(h2, h3, ph1, pl1);
                *(u32*)(sHh + c0*72 + l) = ph0;
                *(u32*)(sHl + c0*72 + l) = pl0;
                *(u32*)(sHh + (c0 + 8)*72 + l) = ph1;
                *(u32*)(sHl + (c0 + 8)*72 + l) = pl1;
            }
        }
    }

    for (int m = 0; m < 10; ++m){
        __syncthreads();
#pragma unroll
        for (int i = 0; i < 4; ++i){
            int idx = i*128 + tid;
            int row = idx >> 3, seg = idx & 7;
            *(uint4*)(sWh + row*72 + seg*8) = *(const uint4*)(g_Wqh + m*4096 + row*64 + seg*8);
            *(uint4*)(sWl + row*72 + seg*8) = *(const uint4*)(g_Wql + m*4096 + row*64 + seg*8);
        }
        __syncthreads();

        float a2[8][4];
#pragma unroll
        for (int j = 0; j < 8; ++j)
#pragma unroll
            for (int e = 0; e < 4; ++e) a2[j][e] = 0.f;

#pragma unroll
        for (int ks = 0; ks < 64; ks += 16){
            u32 ah[4], al[4];
            u32 ao = (u32)((wid*16 + (lane & 15))*72 + ks + (lane >> 4)*8)*2;
            ldmA(ah, uWh + ao);
            ldmA(al, uWl + ao);
            int brow = ks + (lane & 15), bcol = (lane >> 4)*8;
#pragma unroll
            for (int g = 0; g < 4; ++g){
                u32 bh[4], bl[4];
                u32 bo = (u32)(brow*72 + g*16 + bcol)*2;
                ldmBT(bh, uHh + bo);
                ldmBT(bl, uHl + bo);
#pragma unroll
                for (int h = 0; h < 2; ++h){
                    float* c = a2[g*2 + h];
                    mma16816(c, ah, bh[2*h], bh[2*h+1]);
                    mma16816(c, ah, bl[2*h], bl[2*h+1]);
                    mma16816(c, al, bh[2*h], bh[2*h+1]);
                }
            }
        }

        int cp = wid*16 + rbase;
        if (m == 4 || m == 9){
            __nv_bfloat16* wh = g_bf + (u64)(m == 4 ? 0 : 6)*BUFSZ;
            __nv_bfloat16* wl = wh + BUFSZ;
            int bcA = b*64 + cp, bcB = bcA + 8;
#pragma unroll
            for (int jj = 0; jj < 8; ++jj){
                int l = jj*8 + lbase;
                float* c = a2[jj];
                u32 h0, l0, h1, l1;
                split2(c[0], c[1], h0, l0);
                split2(c[2], c[3], h1, l1);
                u64 o1 = boff(bcA, n, l), o2 = boff(bcB, n, l);
                *(u32*)(wh + o1) = h0;
                *(u32*)(wl + o1) = l0;
                *(u32*)(wh + o2) = h1;
                *(u32*)(wl + o2) = l1;
            }
        } else {
            float* dst = g_pool + (u64)m*BUFSZ;
            u64 eoff0 = ((u64)(b*64 + cp)*512 + n)*64;
            u64 eoff1 = ((u64)(b*64 + cp + 8)*512 + n)*64;
#pragma unroll
            for (int jj = 0; jj < 8; ++jj){
                int l = jj*8 + lbase;
                float* c = a2[jj];
                *(float2*)(dst + eoff0 + l) = make_float2(c[0], c[1]);
                *(float2*)(dst + eoff1 + l) = make_float2(c[2], c[3]);
            }
        }
    }
}

// ---------------------------------------------------------------------------
// tensor-core node step: r' = q + d∘r + A'·r  (ONE product A'h·rh)
// 128 threads, tile 64v x 128l (wy = wid&1 selects 32v half, wx = wid>>1 bc).
// 3-stage pipeline, cp.async.bulk (A 4KB + 2x B 4KB per chunk, ONE issuing
// thread) with per-stage mbarrier; one __syncthreads per chunk. 4 CTAs/SM.
// Stage layout (12288B): [A 4096][B_bc0 4096][B_bc1 4096].
// MODE 0: write r' bf16 hi/lo (swizzled); MODE 1: fp32 ACC; MODE 2: output.
// ---------------------------------------------------------------------------
#define NODE_SST 12288
#define NODE_SMEM (3*NODE_SST)

__device__ __forceinline__ void node_issue(u32 sb, u32 mb,
        const __nv_bfloat16* Ah, const __nv_bfloat16* Bh0,
        int kc, int v0c, int bc0){
    mbar_expect(mb, 12288u);
    bulkcp(sb,        Ah  + (u64)kc*16384 + (u64)v0c*32,        4096, mb);
    bulkcp(sb + 4096, Bh0 + (u64)bc0*32768 + (u64)kc*2048,      4096, mb);
    bulkcp(sb + 8192, Bh0 + (u64)(bc0+1)*32768 + (u64)kc*2048,  4096, mb);
}

template<int MODE>
__global__ __launch_bounds__(128, 4)
void k_node_mma(int asel, int qid, int bslot, int wslot, float* __restrict__ outp){
    extern __shared__ __align__(16) char smn[];
    __shared__ __align__(8) u64 s_mb[3];
    u32 base = smem_u32(smn);

    int z = blockIdx.z;
    asel += z; qid += 5*z; bslot += 6*z; wslot += 6*z;

    int tid = threadIdx.x, lane = tid & 31, wid = tid >> 5;
    int wy = wid & 1, wx = wid >> 1;
    int bc0 = blockIdx.x*2, v0c = blockIdx.y << 6;

    const __nv_bfloat16* Ah  = g_Abf + (u64)asel*262144;
    const __nv_bfloat16* Bh0 = g_bf + (u64)bslot*BUFSZ;
    const float* dvec = g_dA + asel*512;

    if (tid == 0){
        mbar_init(smem_u32(&s_mb[0]), 1);
        mbar_init(smem_u32(&s_mb[1]), 1);
        mbar_init(smem_u32(&s_mb[2]), 1);
    }
    __syncthreads();
    if (tid == 0){
        node_issue(base,            smem_u32(&s_mb[0]), Ah, Bh0, 0, v0c, bc0);
        node_issue(base + NODE_SST, smem_u32(&s_mb[1]), Ah, Bh0, 1, v0c, bc0);
    }

    float acc[2][8][4];
#pragma unroll
    for (int m = 0; m < 2; ++m)
#pragma unroll
        for (int j = 0; j < 8; ++j)
#pragma unroll
            for (int e = 0; e < 4; ++e) acc[m][j][e] = 0.f;

    int st = 0, pst = 2;
    for (int kc = 0; kc < 16; ++kc){
        mbar_wait(smem_u32(&s_mb[st]), (kc/3)&1);
        __syncthreads();   // all warps finished MMA on stage (kc-1)%3 == pst
        if (tid == 0 && kc + 2 < 16)
            node_issue(base + pst*NODE_SST, smem_u32(&s_mb[pst]),
                       Ah, Bh0, kc + 2, v0c, bc0);

        u32 sb = base + st*NODE_SST;
        u32 uA = sb, uB = sb + 4096 + (wx << 12);
#pragma unroll
        for (int ks = 0; ks < 32; ks += 16){
            u32 ah[2][4];
            int arow = lane & 15;
            int uk = (ks >> 3) + (lane >> 4);          // 0..3 (16B unit in k)
#pragma unroll
            for (int m = 0; m < 2; ++m){
                int row = wy*32 + m*16 + arow;         // 0..63
                u32 ao = (u32)(row*64 + ((uk ^ ((row >> 1) & 3)) << 4));
                ldmA(ah[m], uA + ao);
            }
            int brow = ks + (lane & 15);
            int sbz = brow & 7;
#pragma unroll
            for (int g = 0; g < 4; ++g){
                u32 bh[4];
                int un = (2*g + (lane >> 4)) ^ sbz;
                ldmBT(bh, uB + (u32)(brow*128 + (un << 4)));
#pragma unroll
                for (int m = 0; m < 2; ++m){
#pragma unroll
                    for (int h = 0; h < 2; ++h){
                        float* c = acc[m][g*2 + h];
                        mma16816(c, ah[m], bh[2*h], bh[2*h+1]);
                    }
                }
            }
        }
        st = (st == 2) ? 0 : st + 1;
        pst = (pst == 2) ? 0 : pst + 1;
    }

    int lbase = (lane & 3)*2, rbase = lane >> 2;
    int bcl = bc0 + wx;
    const float* qp = g_pool + (u64)qid*BUFSZ + (u64)bcl*32768;
    const __nv_bfloat16* rhp = g_bf + (u64)bslot*BUFSZ;
    const __nv_bfloat16* rlp = rhp + BUFSZ;
#pragma unroll
    for (int m = 0; m < 2; ++m){
        int v = v0c + wy*32 + m*16 + rbase;
        float d0 = dvec[v], d1 = dvec[v + 8];
#pragma unroll
        for (int jj = 0; jj < 8; ++jj){
            int l = jj*8 + lbase;
            float* c = acc[m][jj];
            float2 q0 = *(const float2*)(qp + (u64)v*64 + l);
            float2 q1 = *(const float2*)(qp + (u64)(v+8)*64 + l);
            u64 o1 = boff(bcl, v, l), o2 = boff(bcl, v + 8, l);
            float2 r0h = bf2f2(*(const u32*)(rhp + o1));
            float2 r0l = bf2f2(*(const u32*)(rlp + o1));
            float2 r1h = bf2f2(*(const u32*)(rhp + o2));
            float2 r1l = bf2f2(*(const u32*)(rlp + o2));
            float a0 = c[0] + q0.x + d0*(r0h.x + r0l.x);
            float a1 = c[1] + q0.y + d0*(r0h.y + r0l.y);
            float a2 = c[2] + q1.x + d1*(r1h.x + r1l.x);
            float a3 = c[3] + q1.y + d1*(r1h.y + r1l.y);
            if (MODE == 0){
                __nv_bfloat16* wh = g_bf + (u64)wslot*BUFSZ;
                __nv_bfloat16* wl = wh + BUFSZ;
                u32 h0, l0, h1, l1;
                split2(a0, a1, h0, l0);
                split2(a2, a3, h1, l1);
                u64 w1 = boff(bcl, v, l), w2 = boff(bcl, v + 8, l);
                *(u32*)(wh + w1) = h0;
                *(u32*)(wl + w1) = l0;
                *(u32*)(wh + w2) = h1;
                *(u32*)(wl + w2) = l1;
            } else if (MODE == 1){
                float* op = g_pool + 12ULL*BUFSZ + (u64)bcl*32768;
                *(float2*)(op + (u64)v*64 + l) = make_float2(a0, a1);
                *(float2*)(op + (u64)(v+8)*64 + l) = make_float2(a2, a3);
            } else {
                const float* ap = g_pool + 12ULL*BUFSZ + (u64)bcl*32768;
                float bia = g_bias[bcl & 63];
                float* op = outp + (u64)bcl*32768;
                a0 += ap[(u64)v*64 + l] + bia;
                a1 += ap[(u64)v*64 + l + 1] + bia;
                a2 += ap[(u64)(v+8)*64 + l] + bia;
                a3 += ap[(u64)(v+8)*64 + l + 1] + bia;
                if (l < 58)     op[(u64)v*64 + l + 6]       = a0;
                if (l + 1 < 58) op[(u64)v*64 + l + 7]       = a1;
                if (l < 58)     op[(u64)(v+8)*64 + l + 6]   = a2;
                if (l + 1 < 58) op[(u64)(v+8)*64 + l + 7]   = a3;
            }
        }
    }
}

__global__ void k_zeropad(float* __restrict__ outp){
    int i = blockIdx.x*256 + threadIdx.x;
    if (i < 8*64*512*6){
        int row = i / 6, t = i - row*6;
        outp[(u64)row*64 + t] = 0.f;
    }
}

// ---------------------------------------------------------------------------
extern "C" void kernel_launch(void* const* d_in, const int* in_sizes, int n_in,
                              void* d_out, int out_size){
    (void)in_sizes; (void)n_in; (void)out_size;
    const float* x   = (const float*)d_in[0];
    const float* adj = (const float*)d_in[1];
    float* out = (float*)d_out;

    cudaFuncSetAttribute(k_node_mma<0>, cudaFuncAttributeMaxDynamicSharedMemorySize, NODE_SMEM);
    cudaFuncSetAttribute(k_node_mma<1>, cudaFuncAttributeMaxDynamicSharedMemorySize, NODE_SMEM);
    cudaFuncSetAttribute(k_node_mma<2>, cudaFuncAttributeMaxDynamicSharedMemorySize, NODE_SMEM);

    k_deg  <<<512, 256>>>(adj);
    k_norm <<<512, 256>>>(adj);
    k_prepA<<<512, 256>>>();
    k_prep<<<64, 256>>>(
        (const float*)d_in[ 2], (const float*)d_in[ 3], (const float*)d_in[ 4], (const float*)d_in[ 5],
        (const float*)d_in[ 6], (const float*)d_in[ 7], (const float*)d_in[ 8], (const float*)d_in[ 9],
        (const float*)d_in[10], (const float*)d_in[11], (const float*)d_in[12], (const float*)d_in[13],
        (const float*)d_in[14], (const float*)d_in[15], (const float*)d_in[16], (const float*)d_in[17],
        (const float*)d_in[18], (const float*)d_in[19], (const float*)d_in[20], (const float*)d_in[21]);

    k_fused<<<4096, 128>>>(x);

    // Horner: branch0 seed slot 0 (q4), branch1 seed slot 6 (q9);
    // merged launches run both branches via gridDim.z = 2.
    dim3 ng3(256, 8, 2);
    k_node_mma<0><<<ng3, 128, NODE_SMEM>>>(0, 3, 0, 2, nullptr);   // step 0
    k_node_mma<0><<<ng3, 128, NODE_SMEM>>>(0, 2, 2, 4, nullptr);   // step 1
    k_node_mma<0><<<ng3, 128, NODE_SMEM>>>(0, 1, 4, 2, nullptr);   // step 2
    dim3 ng(256, 8, 1);
    k_node_mma<1><<<ng, 128, NODE_SMEM>>>(0, 0, 2, 0, nullptr);    // b0 final -> ACC
    k_node_mma<2><<<ng, 128, NODE_SMEM>>>(1, 5, 8, 0, out);        // b1 final -> out

    k_zeropad<<<6144, 256>>>(out);
}